// round 6
// baseline (speedup 1.0000x reference)
#include <cuda_runtime.h>
#include <math.h>

// ---------------------------------------------------------------------------
// Scratch (no allocs allowed -> __device__ globals)
// ---------------------------------------------------------------------------
__device__ float g_bufA[4096 * 2048];
__device__ float g_bufB[4096 * 2048];

// ---------------------------------------------------------------------------
// SGEMM: C[M,N] = A[M,K] @ B[K,N] + bias[N]   (all row-major, fp32)
// 128x128 block tile, BK=8, 8x8 per thread, 256 threads.
// M % 128 == 0 and K % 8 == 0 are guaranteed by the launch shapes.
// N may be ragged (N=1000) -> guarded loads/stores on the N edge.
// ---------------------------------------------------------------------------
constexpr int BM = 128, BN = 128, BK = 8, TM = 8, TN = 8;

__global__ __launch_bounds__(256) void sgemm_bias(
    int M, int N, int K,
    const float* __restrict__ A, const float* __restrict__ B,
    const float* __restrict__ bias, float* __restrict__ C)
{
    __shared__ __align__(16) float As[BK][BM];
    __shared__ __align__(16) float Bs[BK][BN];

    const int tid = threadIdx.x;
    const int bm  = blockIdx.y * BM;
    const int bn  = blockIdx.x * BN;
    const int ty  = tid / (BN / TN);   // 0..15
    const int tx  = tid % (BN / TN);   // 0..15

    float acc[TM][TN];
    #pragma unroll
    for (int i = 0; i < TM; i++)
        #pragma unroll
        for (int j = 0; j < TN; j++)
            acc[i][j] = 0.0f;

    // Loader assignments: each thread loads one float4 of A and one of B
    const int am  = tid >> 1;           // 0..127
    const int ak  = (tid & 1) * 4;      // 0 or 4
    const int bk  = tid >> 5;           // 0..7
    const int bn4 = (tid & 31) * 4;     // 0..124

    for (int k0 = 0; k0 < K; k0 += BK) {
        // A tile (K divisible by 4 in all call sites -> aligned float4)
        float4 av = *reinterpret_cast<const float4*>(
            &A[(size_t)(bm + am) * K + k0 + ak]);
        As[ak + 0][am] = av.x;
        As[ak + 1][am] = av.y;
        As[ak + 2][am] = av.z;
        As[ak + 3][am] = av.w;

        // B tile (guard the N edge)
        int col = bn + bn4;
        if (col + 3 < N) {
            float4 bv = *reinterpret_cast<const float4*>(
                &B[(size_t)(k0 + bk) * N + col]);
            Bs[bk][bn4 + 0] = bv.x;
            Bs[bk][bn4 + 1] = bv.y;
            Bs[bk][bn4 + 2] = bv.z;
            Bs[bk][bn4 + 3] = bv.w;
        } else {
            #pragma unroll
            for (int e = 0; e < 4; e++)
                Bs[bk][bn4 + e] = (col + e < N)
                    ? B[(size_t)(k0 + bk) * N + col + e] : 0.0f;
        }
        __syncthreads();

        #pragma unroll
        for (int kk = 0; kk < BK; kk++) {
            float4 a0 = *reinterpret_cast<const float4*>(&As[kk][ty * TM]);
            float4 a1 = *reinterpret_cast<const float4*>(&As[kk][ty * TM + 4]);
            float4 b0 = *reinterpret_cast<const float4*>(&Bs[kk][tx * TN]);
            float4 b1 = *reinterpret_cast<const float4*>(&Bs[kk][tx * TN + 4]);
            float ra[TM] = {a0.x, a0.y, a0.z, a0.w, a1.x, a1.y, a1.z, a1.w};
            float rb[TN] = {b0.x, b0.y, b0.z, b0.w, b1.x, b1.y, b1.z, b1.w};
            #pragma unroll
            for (int i = 0; i < TM; i++)
                #pragma unroll
                for (int j = 0; j < TN; j++)
                    acc[i][j] += ra[i] * rb[j];
        }
        __syncthreads();
    }

    #pragma unroll
    for (int i = 0; i < TM; i++) {
        int rowc = bm + ty * TM + i;
        #pragma unroll
        for (int j = 0; j < TN; j++) {
            int col = bn + tx * TN + j;
            if (col < N)
                C[(size_t)rowc * N + col] = acc[i][j] + bias[col];
        }
    }
}

// ---------------------------------------------------------------------------
// Quantum circuit kernel: one block per batch row.
// AmplitudeEmbedding(normalize) + 3x StronglyEntanglingLayers + probs.
// wire q  <->  bit (9 - q) of the flat amplitude index (wire 0 = MSB).
// Rot(phi,theta,omega) needs only 4 scalars:
//   A = cos(a)cos(t/2), B = sin(a)cos(t/2), Cc = cos(b)sin(t/2), D = sin(b)sin(t/2)
// with a = (phi+omega)/2, b = (phi-omega)/2.
//   U00 = (A,-B)  U01 = (-Cc,-D)  U10 = (Cc,-D)  U11 = (A,B)
// ---------------------------------------------------------------------------
__global__ __launch_bounds__(256) void circuit_kernel(
    const float* __restrict__ x,    // [4096, 1024]
    const float* __restrict__ w,    // [3, 10, 3]
    float* __restrict__ out)        // [4096, 1024] probs
{
    __shared__ float sre[1024];
    __shared__ float sim[1024];
    __shared__ float Ug[30][4];
    __shared__ float red[8];

    const int row = blockIdx.x;
    const int tid = threadIdx.x;

    // Precompute all 30 gate matrices (threads 0..29)
    if (tid < 30) {
        float phi = w[tid * 3 + 0];
        float th  = w[tid * 3 + 1];
        float om  = w[tid * 3 + 2];
        float s, c;   sincosf(0.5f * th, &s, &c);
        float sa, ca; sincosf(0.5f * (phi + om), &sa, &ca);
        float sb, cb; sincosf(0.5f * (phi - om), &sb, &cb);
        Ug[tid][0] = ca * c;  // A
        Ug[tid][1] = sa * c;  // B
        Ug[tid][2] = cb * s;  // Cc
        Ug[tid][3] = sb * s;  // D
    }

    // Load row, compute L2 norm, write normalized state into smem
    float v[4];
    float ss = 0.0f;
    #pragma unroll
    for (int j = 0; j < 4; j++) {
        v[j] = x[(size_t)row * 1024 + tid + j * 256];
        ss += v[j] * v[j];
    }
    #pragma unroll
    for (int o = 16; o > 0; o >>= 1)
        ss += __shfl_xor_sync(0xFFFFFFFFu, ss, o);
    if ((tid & 31) == 0) red[tid >> 5] = ss;
    __syncthreads();
    float tot = 0.0f;
    #pragma unroll
    for (int j = 0; j < 8; j++) tot += red[j];
    float inv = rsqrtf(tot);
    #pragma unroll
    for (int j = 0; j < 4; j++) {
        sre[tid + j * 256] = v[j] * inv;
        sim[tid + j * 256] = 0.0f;
    }
    __syncthreads();

    for (int l = 0; l < 3; l++) {
        // --- single-qubit rotations ---
        for (int q = 0; q < 10; q++) {
            const int g = l * 10 + q;
            const float Am = Ug[g][0], Bm = Ug[g][1];
            const float Cm = Ug[g][2], Dm = Ug[g][3];
            const int bit = 9 - q;
            const int mask = 1 << bit;
            #pragma unroll
            for (int p = tid; p < 512; p += 256) {
                int lo = p & (mask - 1);
                int i0 = ((p - lo) << 1) | lo;
                int i1 = i0 | mask;
                float a0r = sre[i0], a0i = sim[i0];
                float a1r = sre[i1], a1i = sim[i1];
                sre[i0] = Am * a0r + Bm * a0i - Cm * a1r + Dm * a1i;
                sim[i0] = Am * a0i - Bm * a0r - Cm * a1i - Dm * a1r;
                sre[i1] = Cm * a0r + Dm * a0i + Am * a1r - Bm * a1i;
                sim[i1] = Cm * a0i - Dm * a0r + Am * a1i + Bm * a1r;
            }
            __syncthreads();
        }
        // --- CNOT ring, range r = l % 9 + 1 (sequential, non-commuting) ---
        const int r = l % 9 + 1;
        for (int q = 0; q < 10; q++) {
            const int cb = 9 - q;
            const int tb = 9 - ((q + r) % 10);
            const int cmask = 1 << cb;
            const int tmask = 1 << tb;
            const int b1 = cb < tb ? cb : tb;
            const int b2 = cb < tb ? tb : cb;
            // 256 indices with control=1, target=0 : one swap per thread
            int p  = tid;
            int lo = p & ((1 << b1) - 1);
            int mid = (p >> b1) & ((1 << (b2 - b1 - 1)) - 1);
            int hi = p >> (b2 - 1);
            int idx = (hi << (b2 + 1)) | (mid << (b1 + 1)) | lo | cmask;
            int j2 = idx | tmask;
            float tr = sre[idx], ti = sim[idx];
            sre[idx] = sre[j2]; sim[idx] = sim[j2];
            sre[j2] = tr;       sim[j2] = ti;
            __syncthreads();
        }
    }

    // probs
    #pragma unroll
    for (int j = 0; j < 4; j++) {
        int i = tid + j * 256;
        out[(size_t)row * 1024 + i] = sre[i] * sre[i] + sim[i] * sim[i];
    }
}

// ---------------------------------------------------------------------------
// Final: y = |x| ; y /= rowsum(y)        x: [4096, 1000]
// ---------------------------------------------------------------------------
__global__ __launch_bounds__(256) void abs_norm_kernel(
    const float* __restrict__ x, float* __restrict__ out)
{
    __shared__ float red[8];
    const int row = blockIdx.x;
    const int tid = threadIdx.x;

    float v[4];
    float ss = 0.0f;
    #pragma unroll
    for (int j = 0; j < 4; j++) {
        int i = tid + j * 256;
        v[j] = (i < 1000) ? fabsf(x[(size_t)row * 1000 + i]) : 0.0f;
        ss += v[j];
    }
    #pragma unroll
    for (int o = 16; o > 0; o >>= 1)
        ss += __shfl_xor_sync(0xFFFFFFFFu, ss, o);
    if ((tid & 31) == 0) red[tid >> 5] = ss;
    __syncthreads();
    float tot = 0.0f;
    #pragma unroll
    for (int j = 0; j < 8; j++) tot += red[j];
    float inv = 1.0f / tot;
    #pragma unroll
    for (int j = 0; j < 4; j++) {
        int i = tid + j * 256;
        if (i < 1000)
            out[(size_t)row * 1000 + i] = v[j] * inv;
    }
}

// ---------------------------------------------------------------------------
// Launch
// ---------------------------------------------------------------------------
extern "C" void kernel_launch(void* const* d_in, const int* in_sizes, int n_in,
                              void* d_out, int out_size)
{
    const float* inputs = (const float*)d_in[0];
    const float* wEnc   = (const float*)d_in[1];
    const float* wDec   = (const float*)d_in[2];
    const float* W0     = (const float*)d_in[3];
    const float* b0     = (const float*)d_in[4];
    const float* W1     = (const float*)d_in[5];
    const float* b1     = (const float*)d_in[6];
    const float* W2     = (const float*)d_in[7];
    const float* b2     = (const float*)d_in[8];
    const float* W3     = (const float*)d_in[9];
    const float* b3     = (const float*)d_in[10];
    float* outp = (float*)d_out;

    float *bufA = nullptr, *bufB = nullptr;
    cudaGetSymbolAddress((void**)&bufA, g_bufA);
    cudaGetSymbolAddress((void**)&bufB, g_bufB);

    dim3 blk(256);

    // x = inputs @ W0 + b0                      [4096,1024]
    sgemm_bias<<<dim3(8, 32), blk>>>(4096, 1024, 1000, inputs, W0, b0, bufA);
    // x = circuit(x, wEnc)                      [4096,1024]
    circuit_kernel<<<4096, blk>>>(bufA, wEnc, bufB);
    // x = x @ W1 + b1                           [4096,2048]
    sgemm_bias<<<dim3(16, 32), blk>>>(4096, 2048, 1024, bufB, W1, b1, bufA);
    // x = x @ W2 + b2                           [4096,1024]
    sgemm_bias<<<dim3(8, 32), blk>>>(4096, 1024, 2048, bufA, W2, b2, bufB);
    // x = circuit(x, wDec)                      [4096,1024]
    circuit_kernel<<<4096, blk>>>(bufB, wDec, bufA);
    // x = x @ W3 + b3                           [4096,1000]
    sgemm_bias<<<dim3(8, 32), blk>>>(4096, 1000, 1024, bufA, W3, b3, bufB);
    // out = |x| / rowsum(|x|)
    abs_norm_kernel<<<4096, blk>>>(bufB, outp);
}

// round 9
// speedup vs baseline: 2.4013x; 2.4013x over previous
#include <cuda_runtime.h>
#include <cuda_bf16.h>
#include <cstdint>
#include <math.h>

// ---------------------------------------------------------------------------
// Scratch (no allocs allowed -> __device__ globals)
// ---------------------------------------------------------------------------
__device__ float g_bufA[4096 * 2048];
__device__ float g_bufB[4096 * 2048];
__device__ __nv_bfloat16 g_actx[4096 * 6144];   // extended activations [M, 3*K_pad]
__device__ __nv_bfloat16 g_w0x[1024 * 3072];    // W^T extended [N_pad, 3*K_pad]
__device__ __nv_bfloat16 g_w1x[2048 * 3072];
__device__ __nv_bfloat16 g_w2x[1024 * 6144];
__device__ __nv_bfloat16 g_w3x[1024 * 3072];
__device__ float g_bias3[1024];

// ---------------------------------------------------------------------------
// PTX helpers (baseline sm_80+ features only: cp.async, ldmatrix, mma.sync)
// ---------------------------------------------------------------------------
__device__ __forceinline__ uint32_t smem_u32(const void* p) {
    uint32_t a;
    asm("{ .reg .u64 t; cvta.to.shared.u64 t, %1; cvt.u32.u64 %0, t; }"
        : "=r"(a) : "l"(p));
    return a;
}

#define CP_ASYNC16(dst_u32, src_ptr)                                          \
    asm volatile("cp.async.cg.shared.global [%0], [%1], 16;"                  \
                 :: "r"(dst_u32), "l"(src_ptr))
#define CP_COMMIT() asm volatile("cp.async.commit_group;" ::: "memory")
#define CP_WAIT(n)  asm volatile("cp.async.wait_group %0;" :: "n"(n) : "memory")

#define LDSM_X4(r0, r1, r2, r3, addr)                                         \
    asm volatile("ldmatrix.sync.aligned.m8n8.x4.shared.b16 {%0,%1,%2,%3}, [%4];" \
                 : "=r"(r0), "=r"(r1), "=r"(r2), "=r"(r3) : "r"(addr))

#define MMA_16816(d, a, b)                                                    \
    asm volatile(                                                             \
        "mma.sync.aligned.m16n8k16.row.col.f32.bf16.bf16.f32 "                \
        "{%0,%1,%2,%3}, {%4,%5,%6,%7}, {%8,%9}, {%0,%1,%2,%3};"               \
        : "+f"((d)[0]), "+f"((d)[1]), "+f"((d)[2]), "+f"((d)[3])              \
        : "r"((a)[0]), "r"((a)[1]), "r"((a)[2]), "r"((a)[3]),                 \
          "r"((b)[0]), "r"((b)[1]))

// ---------------------------------------------------------------------------
// Conversion kernels: fp32 -> extended bf16 (hi|lo|hi for A, hi|hi|lo for B)
// ---------------------------------------------------------------------------
__global__ __launch_bounds__(256) void convert_act(
    const float* __restrict__ in, __nv_bfloat16* __restrict__ out,
    int K_in, int K_pad)
{
    int idx = blockIdx.x * 256 + threadIdx.x;     // over rows * K_pad
    int r = idx / K_pad;
    int k = idx - r * K_pad;
    float x = (k < K_in) ? in[(size_t)r * K_in + k] : 0.0f;
    __nv_bfloat16 hi = __float2bfloat16(x);
    __nv_bfloat16 lo = __float2bfloat16(x - __bfloat162float(hi));
    size_t base = (size_t)r * 3 * K_pad;
    out[base + k] = hi;                 // hi block
    out[base + K_pad + k] = lo;         // lo block  (pairs with B's hi)
    out[base + 2 * K_pad + k] = hi;     // hi block  (pairs with B's lo)
}

// W [K_in, N_in] row-major  ->  out [N_pad, 3*K_pad] (transposed, hi|hi|lo)
__global__ __launch_bounds__(256) void convert_weight(
    const float* __restrict__ W, __nv_bfloat16* __restrict__ out,
    int K_in, int N_in, int K_pad, int N_pad)
{
    __shared__ float t[32][33];
    int k0 = blockIdx.x * 32, n0 = blockIdx.y * 32;
    int tx = threadIdx.x & 31, ty = threadIdx.x >> 5;   // ty 0..7
    #pragma unroll
    for (int i = 0; i < 32; i += 8) {
        int k = k0 + ty + i, n = n0 + tx;
        t[ty + i][tx] = (k < K_in && n < N_in) ? W[(size_t)k * N_in + n] : 0.0f;
    }
    __syncthreads();
    size_t K3 = 3 * (size_t)K_pad;
    #pragma unroll
    for (int i = 0; i < 32; i += 8) {
        int n = n0 + ty + i, k = k0 + tx;
        if (n < N_pad && k < K_pad) {
            float x = t[tx][ty + i];
            __nv_bfloat16 hi = __float2bfloat16(x);
            __nv_bfloat16 lo = __float2bfloat16(x - __bfloat162float(hi));
            __nv_bfloat16* row = out + (size_t)n * K3;
            row[k] = hi;
            row[K_pad + k] = hi;
            row[2 * K_pad + k] = lo;
        }
    }
}

__global__ void pad_bias(const float* __restrict__ b, float* __restrict__ out,
                         int n_in)
{
    int i = blockIdx.x * 256 + threadIdx.x;
    out[i] = (i < n_in) ? b[i] : 0.0f;
}

// ---------------------------------------------------------------------------
// mma.sync GEMM: C[M,N] = A'[M,Kx] @ B'[N,Kx]^T + bias  (bf16 in, fp32 out)
// CTA tile 128x128, BK=64 (128B rows, XOR-swizzled), cp.async double buffer.
// 8 warps: warp tile 64x32 (wm = wid&1, wn = wid>>1).
// grid = (N/128, M/128), 256 threads.
// ---------------------------------------------------------------------------
#define TILE_BYTES 16384          // 128 rows * 128 B
#define BUF_BYTES  (2 * TILE_BYTES)

__global__ __launch_bounds__(256, 2) void gemm_mma(
    int Kx, int ldc,
    const __nv_bfloat16* __restrict__ A, const __nv_bfloat16* __restrict__ B,
    const float* __restrict__ bias, float* __restrict__ C)
{
    extern __shared__ char smem[];
    uint32_t sb = smem_u32(smem);

    const int tid = threadIdx.x;
    const int wid = tid >> 5, lane = tid & 31;
    const int bm = blockIdx.y * 128, bn = blockIdx.x * 128;
    const int wm = (wid & 1) * 64;       // warp M offset in tile
    const int wn = (wid >> 1) * 32;      // warp N offset in tile

    // Global load assignment (4 x 16B per thread per tile)
    const int gr  = tid >> 1;            // base row pairs: actually see below
    (void)gr;

    float d[4][4][4];
    #pragma unroll
    for (int mt = 0; mt < 4; mt++)
        #pragma unroll
        for (int nt = 0; nt < 4; nt++)
            #pragma unroll
            for (int e = 0; e < 4; e++)
                d[mt][nt][e] = 0.0f;

    const int nch = Kx >> 6;

    // ---- loader lambda (cp.async) ----
    auto load_chunk = [&](int ch, int buf) {
        const int kc = ch << 6;
        uint32_t sA = sb + buf * BUF_BYTES;
        uint32_t sB = sA + TILE_BYTES;
        #pragma unroll
        for (int it = 0; it < 4; it++) {
            int f = tid + it * 256;            // 0..1023
            int r = f >> 3, c16 = f & 7;
            uint32_t off = (uint32_t)(r * 128 + c16 * 16);
            off ^= (off >> 3) & 0x70;
            const __nv_bfloat16* srcA = A + (size_t)(bm + r) * Kx + kc + c16 * 8;
            const __nv_bfloat16* srcB = B + (size_t)(bn + r) * Kx + kc + c16 * 8;
            CP_ASYNC16(sA + off, srcA);
            CP_ASYNC16(sB + off, srcB);
        }
    };

    load_chunk(0, 0);
    CP_COMMIT();

    for (int ch = 0; ch < nch; ch++) {
        const int cur = ch & 1;
        if (ch + 1 < nch) {
            load_chunk(ch + 1, cur ^ 1);
            CP_COMMIT();
            CP_WAIT(1);
        } else {
            CP_WAIT(0);
        }
        __syncthreads();

        uint32_t sA = sb + cur * BUF_BYTES;
        uint32_t sB = sA + TILE_BYTES;

        #pragma unroll
        for (int s = 0; s < 4; s++) {          // 4 k16-steps in BK=64
            uint32_t a[4][4];
            uint32_t b[4][2];
            // A fragments: 4 m-tiles of 16 rows
            #pragma unroll
            for (int mt = 0; mt < 4; mt++) {
                int row = wm + mt * 16 + (lane & 7) + ((lane >> 3) & 1) * 8;
                int colb = s * 32 + ((lane >> 4) & 1) * 16;
                uint32_t off = (uint32_t)(row * 128 + colb);
                off ^= (off >> 3) & 0x70;
                LDSM_X4(a[mt][0], a[mt][1], a[mt][2], a[mt][3], sA + off);
            }
            // B fragments: 2 x ldmatrix.x4 cover 4 n-tiles of 8 cols
            #pragma unroll
            for (int nt2 = 0; nt2 < 2; nt2++) {
                int row = wn + nt2 * 16 + ((lane >> 4) & 1) * 8 + (lane & 7);
                int colb = s * 32 + ((lane >> 3) & 1) * 16;
                uint32_t off = (uint32_t)(row * 128 + colb);
                off ^= (off >> 3) & 0x70;
                uint32_t r0, r1, r2, r3;
                LDSM_X4(r0, r1, r2, r3, sB + off);
                b[nt2 * 2 + 0][0] = r0; b[nt2 * 2 + 0][1] = r1;
                b[nt2 * 2 + 1][0] = r2; b[nt2 * 2 + 1][1] = r3;
            }
            #pragma unroll
            for (int mt = 0; mt < 4; mt++)
                #pragma unroll
                for (int nt = 0; nt < 4; nt++)
                    MMA_16816(d[mt][nt], a[mt], b[nt]);
        }
        __syncthreads();
    }

    // Epilogue: d[mt][nt] mapping: d0:(r,c) d1:(r,c+1) d2:(r+8,c) d3:(r+8,c+1)
    // r = lane>>2, c = (lane&3)*2
    const int er = lane >> 2;
    const int ec = (lane & 3) * 2;
    #pragma unroll
    for (int nt = 0; nt < 4; nt++) {
        int col = bn + wn + nt * 8 + ec;
        float b0 = bias[col], b1 = bias[col + 1];
        #pragma unroll
        for (int mt = 0; mt < 4; mt++) {
            int row = bm + wm + mt * 16 + er;
            float2 v0 = make_float2(d[mt][nt][0] + b0, d[mt][nt][1] + b1);
            float2 v1 = make_float2(d[mt][nt][2] + b0, d[mt][nt][3] + b1);
            *reinterpret_cast<float2*>(C + (size_t)row * ldc + col) = v0;
            *reinterpret_cast<float2*>(C + (size_t)(row + 8) * ldc + col) = v1;
        }
    }
}

// ---------------------------------------------------------------------------
// Quantum circuit kernel: one block per batch row.
// ---------------------------------------------------------------------------
__global__ __launch_bounds__(256) void circuit_kernel(
    const float* __restrict__ x,    // [4096, 1024]
    const float* __restrict__ w,    // [3, 10, 3]
    float* __restrict__ out)        // [4096, 1024] probs
{
    __shared__ float sre[1024];
    __shared__ float sim[1024];
    __shared__ float Ug[30][4];
    __shared__ float red[8];

    const int row = blockIdx.x;
    const int tid = threadIdx.x;

    if (tid < 30) {
        float phi = w[tid * 3 + 0];
        float th  = w[tid * 3 + 1];
        float om  = w[tid * 3 + 2];
        float s, c;   sincosf(0.5f * th, &s, &c);
        float sa, ca; sincosf(0.5f * (phi + om), &sa, &ca);
        float sb, cb; sincosf(0.5f * (phi - om), &sb, &cb);
        Ug[tid][0] = ca * c;
        Ug[tid][1] = sa * c;
        Ug[tid][2] = cb * s;
        Ug[tid][3] = sb * s;
    }

    float v[4];
    float ss = 0.0f;
    #pragma unroll
    for (int j = 0; j < 4; j++) {
        v[j] = x[(size_t)row * 1024 + tid + j * 256];
        ss += v[j] * v[j];
    }
    #pragma unroll
    for (int o = 16; o > 0; o >>= 1)
        ss += __shfl_xor_sync(0xFFFFFFFFu, ss, o);
    if ((tid & 31) == 0) red[tid >> 5] = ss;
    __syncthreads();
    float tot = 0.0f;
    #pragma unroll
    for (int j = 0; j < 8; j++) tot += red[j];
    float inv = rsqrtf(tot);
    #pragma unroll
    for (int j = 0; j < 4; j++) {
        sre[tid + j * 256] = v[j] * inv;
        sim[tid + j * 256] = 0.0f;
    }
    __syncthreads();

    for (int l = 0; l < 3; l++) {
        for (int q = 0; q < 10; q++) {
            const int g = l * 10 + q;
            const float Am = Ug[g][0], Bm = Ug[g][1];
            const float Cm = Ug[g][2], Dm = Ug[g][3];
            const int bit = 9 - q;
            const int mask = 1 << bit;
            #pragma unroll
            for (int p = tid; p < 512; p += 256) {
                int lo = p & (mask - 1);
                int i0 = ((p - lo) << 1) | lo;
                int i1 = i0 | mask;
                float a0r = sre[i0], a0i = sim[i0];
                float a1r = sre[i1], a1i = sim[i1];
                sre[i0] = Am * a0r + Bm * a0i - Cm * a1r + Dm * a1i;
                sim[i0] = Am * a0i - Bm * a0r - Cm * a1i - Dm * a1r;
                sre[i1] = Cm * a0r + Dm * a0i + Am * a1r - Bm * a1i;
                sim[i1] = Cm * a0i - Dm * a0r + Am * a1i + Bm * a1r;
            }
            __syncthreads();
        }
        const int r = l % 9 + 1;
        for (int q = 0; q < 10; q++) {
            const int cb = 9 - q;
            const int tb = 9 - ((q + r) % 10);
            const int cmask = 1 << cb;
            const int tmask = 1 << tb;
            const int b1 = cb < tb ? cb : tb;
            const int b2 = cb < tb ? tb : cb;
            int p  = tid;
            int lo = p & ((1 << b1) - 1);
            int mid = (p >> b1) & ((1 << (b2 - b1 - 1)) - 1);
            int hi = p >> (b2 - 1);
            int idx = (hi << (b2 + 1)) | (mid << (b1 + 1)) | lo | cmask;
            int j2 = idx | tmask;
            float tr = sre[idx], ti = sim[idx];
            sre[idx] = sre[j2]; sim[idx] = sim[j2];
            sre[j2] = tr;       sim[j2] = ti;
            __syncthreads();
        }
    }

    #pragma unroll
    for (int j = 0; j < 4; j++) {
        int i = tid + j * 256;
        out[(size_t)row * 1024 + i] = sre[i] * sre[i] + sim[i] * sim[i];
    }
}

// ---------------------------------------------------------------------------
// Final: y = |x| ; y /= rowsum(y)   x: [4096, 1024-strided], out: [4096, 1000]
// ---------------------------------------------------------------------------
__global__ __launch_bounds__(256) void abs_norm_kernel(
    const float* __restrict__ x, float* __restrict__ out)
{
    __shared__ float red[8];
    const int row = blockIdx.x;
    const int tid = threadIdx.x;

    float v[4];
    float ss = 0.0f;
    #pragma unroll
    for (int j = 0; j < 4; j++) {
        int i = tid + j * 256;
        v[j] = (i < 1000) ? fabsf(x[(size_t)row * 1024 + i]) : 0.0f;
        ss += v[j];
    }
    #pragma unroll
    for (int o = 16; o > 0; o >>= 1)
        ss += __shfl_xor_sync(0xFFFFFFFFu, ss, o);
    if ((tid & 31) == 0) red[tid >> 5] = ss;
    __syncthreads();
    float tot = 0.0f;
    #pragma unroll
    for (int j = 0; j < 8; j++) tot += red[j];
    float inv = 1.0f / tot;
    #pragma unroll
    for (int j = 0; j < 4; j++) {
        int i = tid + j * 256;
        if (i < 1000)
            out[(size_t)row * 1000 + i] = v[j] * inv;
    }
}

// ---------------------------------------------------------------------------
// Launch
// ---------------------------------------------------------------------------
extern "C" void kernel_launch(void* const* d_in, const int* in_sizes, int n_in,
                              void* d_out, int out_size)
{
    const float* inputs = (const float*)d_in[0];
    const float* wEnc   = (const float*)d_in[1];
    const float* wDec   = (const float*)d_in[2];
    const float* W0     = (const float*)d_in[3];
    const float* b0     = (const float*)d_in[4];
    const float* W1     = (const float*)d_in[5];
    const float* b1     = (const float*)d_in[6];
    const float* W2     = (const float*)d_in[7];
    const float* b2     = (const float*)d_in[8];
    const float* W3     = (const float*)d_in[9];
    const float* b3     = (const float*)d_in[10];
    float* outp = (float*)d_out;

    float *bufA = nullptr, *bufB = nullptr, *bias3 = nullptr;
    __nv_bfloat16 *actx = nullptr, *w0x = nullptr, *w1x = nullptr,
                  *w2x = nullptr, *w3x = nullptr;
    cudaGetSymbolAddress((void**)&bufA, g_bufA);
    cudaGetSymbolAddress((void**)&bufB, g_bufB);
    cudaGetSymbolAddress((void**)&bias3, g_bias3);
    cudaGetSymbolAddress((void**)&actx, g_actx);
    cudaGetSymbolAddress((void**)&w0x, g_w0x);
    cudaGetSymbolAddress((void**)&w1x, g_w1x);
    cudaGetSymbolAddress((void**)&w2x, g_w2x);
    cudaGetSymbolAddress((void**)&w3x, g_w3x);

    dim3 blk(256);
    const int GSMEM = 2 * BUF_BYTES;   // 65536 B dynamic smem (double buffer)
    static bool attr_done = false;
    if (!attr_done) {
        cudaFuncSetAttribute(gemm_mma,
                             cudaFuncAttributeMaxDynamicSharedMemorySize, GSMEM);
        attr_done = true;
    }

    // Weight prep (per-launch, deterministic)
    convert_weight<<<dim3(32, 32), blk>>>(W0, w0x, 1000, 1024, 1024, 1024);
    convert_weight<<<dim3(32, 64), blk>>>(W1, w1x, 1024, 2048, 1024, 2048);
    convert_weight<<<dim3(64, 32), blk>>>(W2, w2x, 2048, 1024, 2048, 1024);
    convert_weight<<<dim3(32, 32), blk>>>(W3, w3x, 1024, 1000, 1024, 1024);
    pad_bias<<<4, blk>>>(b3, bias3, 1000);

    // x = inputs @ W0 + b0                       [4096,1024]
    convert_act<<<4096 * 1024 / 256, blk>>>(inputs, actx, 1000, 1024);
    gemm_mma<<<dim3(8, 32), blk, GSMEM>>>(3072, 1024, actx, w0x, b0, bufA);
    // x = circuit(x, wEnc)
    circuit_kernel<<<4096, blk>>>(bufA, wEnc, bufB);
    // x = x @ W1 + b1                            [4096,2048]
    convert_act<<<4096 * 1024 / 256, blk>>>(bufB, actx, 1024, 1024);
    gemm_mma<<<dim3(16, 32), blk, GSMEM>>>(3072, 2048, actx, w1x, b1, bufA);
    // x = x @ W2 + b2                            [4096,1024]
    convert_act<<<4096 * 2048 / 256, blk>>>(bufA, actx, 2048, 2048);
    gemm_mma<<<dim3(8, 32), blk, GSMEM>>>(6144, 1024, actx, w2x, b2, bufB);
    // x = circuit(x, wDec)
    circuit_kernel<<<4096, blk>>>(bufB, wDec, bufA);
    // x = x @ W3 + b3                            [4096,1024-padded]
    convert_act<<<4096 * 1024 / 256, blk>>>(bufA, actx, 1024, 1024);
    gemm_mma<<<dim3(8, 32), blk, GSMEM>>>(3072, 1024, actx, w3x, bias3, bufB);
    // out = |x| / rowsum(|x|)
    abs_norm_kernel<<<4096, blk>>>(bufB, outp);
}

// round 10
// speedup vs baseline: 2.5303x; 1.0537x over previous
#include <cuda_runtime.h>
#include <cuda_bf16.h>
#include <cstdint>
#include <math.h>

// ---------------------------------------------------------------------------
// Scratch (no allocs allowed -> __device__ globals)
// ---------------------------------------------------------------------------
__device__ float g_bufA[4096 * 1024];
__device__ float g_bufB[4096 * 1024];
__device__ __nv_bfloat16 g_actx[4096 * 6144];    // ext activations [M, 3*2048]
__device__ __nv_bfloat16 g_actx2[4096 * 3072];   // ext activations [M, 3*1024]
__device__ __nv_bfloat16 g_w0x[1024 * 3072];     // W^T extended [N_pad, 3*K_pad]
__device__ __nv_bfloat16 g_w1x[2048 * 3072];
__device__ __nv_bfloat16 g_w2x[1024 * 6144];
__device__ __nv_bfloat16 g_w3x[1024 * 3072];
__device__ float g_bias3[1024];

// ---------------------------------------------------------------------------
// PTX helpers (baseline sm_80+ features only: cp.async, ldmatrix, mma.sync)
// ---------------------------------------------------------------------------
__device__ __forceinline__ uint32_t smem_u32(const void* p) {
    uint32_t a;
    asm("{ .reg .u64 t; cvta.to.shared.u64 t, %1; cvt.u32.u64 %0, t; }"
        : "=r"(a) : "l"(p));
    return a;
}

#define CP_ASYNC16(dst_u32, src_ptr)                                          \
    asm volatile("cp.async.cg.shared.global [%0], [%1], 16;"                  \
                 :: "r"(dst_u32), "l"(src_ptr))
#define CP_COMMIT() asm volatile("cp.async.commit_group;" ::: "memory")
#define CP_WAIT(n)  asm volatile("cp.async.wait_group %0;" :: "n"(n) : "memory")

#define LDSM_X4(r0, r1, r2, r3, addr)                                         \
    asm volatile("ldmatrix.sync.aligned.m8n8.x4.shared.b16 {%0,%1,%2,%3}, [%4];" \
                 : "=r"(r0), "=r"(r1), "=r"(r2), "=r"(r3) : "r"(addr))

#define MMA_16816(d, a, b)                                                    \
    asm volatile(                                                             \
        "mma.sync.aligned.m16n8k16.row.col.f32.bf16.bf16.f32 "                \
        "{%0,%1,%2,%3}, {%4,%5,%6,%7}, {%8,%9}, {%0,%1,%2,%3};"               \
        : "+f"((d)[0]), "+f"((d)[1]), "+f"((d)[2]), "+f"((d)[3])              \
        : "r"((a)[0]), "r"((a)[1]), "r"((a)[2]), "r"((a)[3]),                 \
          "r"((b)[0]), "r"((b)[1]))

// ---------------------------------------------------------------------------
// Conversion kernels: fp32 -> extended bf16 (hi|lo|hi for A, hi|hi|lo for B)
// ---------------------------------------------------------------------------
__global__ __launch_bounds__(256) void convert_act(
    const float* __restrict__ in, __nv_bfloat16* __restrict__ out,
    int K_in, int K_pad)
{
    int idx = blockIdx.x * 256 + threadIdx.x;     // over rows * K_pad
    int r = idx / K_pad;
    int k = idx - r * K_pad;
    float x = (k < K_in) ? in[(size_t)r * K_in + k] : 0.0f;
    __nv_bfloat16 hi = __float2bfloat16(x);
    __nv_bfloat16 lo = __float2bfloat16(x - __bfloat162float(hi));
    size_t base = (size_t)r * 3 * K_pad;
    out[base + k] = hi;                 // hi block
    out[base + K_pad + k] = lo;         // lo block  (pairs with B's hi)
    out[base + 2 * K_pad + k] = hi;     // hi block  (pairs with B's lo)
}

// W [K_in, N_in] row-major  ->  out [N_pad, 3*K_pad] (transposed, hi|hi|lo)
__global__ __launch_bounds__(256) void convert_weight(
    const float* __restrict__ W, __nv_bfloat16* __restrict__ out,
    int K_in, int N_in, int K_pad, int N_pad)
{
    __shared__ float t[32][33];
    int k0 = blockIdx.x * 32, n0 = blockIdx.y * 32;
    int tx = threadIdx.x & 31, ty = threadIdx.x >> 5;   // ty 0..7
    #pragma unroll
    for (int i = 0; i < 32; i += 8) {
        int k = k0 + ty + i, n = n0 + tx;
        t[ty + i][tx] = (k < K_in && n < N_in) ? W[(size_t)k * N_in + n] : 0.0f;
    }
    __syncthreads();
    size_t K3 = 3 * (size_t)K_pad;
    #pragma unroll
    for (int i = 0; i < 32; i += 8) {
        int n = n0 + ty + i, k = k0 + tx;
        if (n < N_pad && k < K_pad) {
            float x = t[tx][ty + i];
            __nv_bfloat16 hi = __float2bfloat16(x);
            __nv_bfloat16 lo = __float2bfloat16(x - __bfloat162float(hi));
            __nv_bfloat16* row = out + (size_t)n * K3;
            row[k] = hi;
            row[K_pad + k] = hi;
            row[2 * K_pad + k] = lo;
        }
    }
}

__global__ void pad_bias(const float* __restrict__ b, float* __restrict__ out,
                         int n_in)
{
    int i = blockIdx.x * 256 + threadIdx.x;
    out[i] = (i < n_in) ? b[i] : 0.0f;
}

// ---------------------------------------------------------------------------
// mma.sync GEMM: C[M,N] = A'[M,Kx] @ B'[N,Kx]^T + bias  (bf16 in)
// CTA tile 128x128, BK=64 (128B rows, XOR-swizzled), cp.async double buffer.
// 4 warps (128 threads), warp tile 64x64. grid = (N/128, M/128).
// mode 0: write fp32 C (ldc stride). mode 1: write extended bf16 hi|lo|hi
//         to C as [row, 3*ldc] (feeds the next GEMM directly).
// ---------------------------------------------------------------------------
#define TILE_BYTES 16384          // 128 rows * 128 B
#define STAGE_BYTES (2 * TILE_BYTES)

__global__ __launch_bounds__(128, 2) void gemm_mma(
    int Kx, int ldc, int mode,
    const __nv_bfloat16* __restrict__ A, const __nv_bfloat16* __restrict__ B,
    const float* __restrict__ bias, void* __restrict__ Cv)
{
    extern __shared__ char smem[];
    uint32_t sb = smem_u32(smem);

    const int tid = threadIdx.x;
    const int wid = tid >> 5, lane = tid & 31;
    const int bm = blockIdx.y * 128, bn = blockIdx.x * 128;
    const int wm = (wid & 1) * 64;       // warp M offset in tile
    const int wn = (wid >> 1) * 64;      // warp N offset in tile

    float d[4][8][4];
    #pragma unroll
    for (int mt = 0; mt < 4; mt++)
        #pragma unroll
        for (int nt = 0; nt < 8; nt++)
            #pragma unroll
            for (int e = 0; e < 4; e++)
                d[mt][nt][e] = 0.0f;

    const int nch = Kx >> 6;

    // ---- loader (cp.async): 32KB per chunk over 128 threads ----
    auto load_chunk = [&](int ch, int buf) {
        const int kc = ch << 6;
        uint32_t sA = sb + buf * STAGE_BYTES;
        uint32_t sB = sA + TILE_BYTES;
        #pragma unroll
        for (int it = 0; it < 8; it++) {
            int f = tid + it * 128;            // 0..1023
            int r = f >> 3, c16 = f & 7;
            uint32_t off = (uint32_t)(r * 128 + c16 * 16);
            off ^= (off >> 3) & 0x70;
            const __nv_bfloat16* srcA = A + (size_t)(bm + r) * Kx + kc + c16 * 8;
            const __nv_bfloat16* srcB = B + (size_t)(bn + r) * Kx + kc + c16 * 8;
            CP_ASYNC16(sA + off, srcA);
            CP_ASYNC16(sB + off, srcB);
        }
    };

    load_chunk(0, 0);
    CP_COMMIT();

    for (int ch = 0; ch < nch; ch++) {
        const int cur = ch & 1;
        if (ch + 1 < nch) {
            load_chunk(ch + 1, cur ^ 1);
            CP_COMMIT();
            CP_WAIT(1);
        } else {
            CP_WAIT(0);
        }
        __syncthreads();

        uint32_t sA = sb + cur * STAGE_BYTES;
        uint32_t sB = sA + TILE_BYTES;

        #pragma unroll
        for (int s = 0; s < 4; s++) {          // 4 k16-steps in BK=64
            uint32_t a[4][4];
            uint32_t b[8][2];
            // A fragments: 4 m-tiles of 16 rows
            #pragma unroll
            for (int mt = 0; mt < 4; mt++) {
                int row = wm + mt * 16 + (lane & 15);
                int colb = s * 32 + ((lane >> 4) & 1) * 16;
                uint32_t off = (uint32_t)(row * 128 + colb);
                off ^= (off >> 3) & 0x70;
                LDSM_X4(a[mt][0], a[mt][1], a[mt][2], a[mt][3], sA + off);
            }
            // B fragments: 4 x ldmatrix.x4 cover 8 n-tiles of 8 cols
            #pragma unroll
            for (int nt2 = 0; nt2 < 4; nt2++) {
                int row = wn + nt2 * 16 + ((lane >> 4) & 1) * 8 + (lane & 7);
                int colb = s * 32 + ((lane >> 3) & 1) * 16;
                uint32_t off = (uint32_t)(row * 128 + colb);
                off ^= (off >> 3) & 0x70;
                uint32_t r0, r1, r2, r3;
                LDSM_X4(r0, r1, r2, r3, sB + off);
                b[nt2 * 2 + 0][0] = r0; b[nt2 * 2 + 0][1] = r1;
                b[nt2 * 2 + 1][0] = r2; b[nt2 * 2 + 1][1] = r3;
            }
            #pragma unroll
            for (int mt = 0; mt < 4; mt++)
                #pragma unroll
                for (int nt = 0; nt < 8; nt++)
                    MMA_16816(d[mt][nt], a[mt], b[nt]);
        }
        __syncthreads();
    }

    // Epilogue. Fragment layout: d0:(r,c) d1:(r,c+1) d2:(r+8,c) d3:(r+8,c+1)
    // with r = lane>>2, c = (lane&3)*2.
    const int er = lane >> 2;
    const int ec = (lane & 3) * 2;
    if (mode == 0) {
        float* C = (float*)Cv;
        #pragma unroll
        for (int nt = 0; nt < 8; nt++) {
            int col = bn + wn + nt * 8 + ec;
            float b0 = bias[col], b1 = bias[col + 1];
            #pragma unroll
            for (int mt = 0; mt < 4; mt++) {
                int row = bm + wm + mt * 16 + er;
                float2 v0 = make_float2(d[mt][nt][0] + b0, d[mt][nt][1] + b1);
                float2 v1 = make_float2(d[mt][nt][2] + b0, d[mt][nt][3] + b1);
                *reinterpret_cast<float2*>(C + (size_t)row * ldc + col) = v0;
                *reinterpret_cast<float2*>(C + (size_t)(row + 8) * ldc + col) = v1;
            }
        }
    } else {
        // Extended bf16 output: [row, 3*ldc] = hi | lo | hi
        __nv_bfloat16* C = (__nv_bfloat16*)Cv;
        const size_t K3 = 3 * (size_t)ldc;
        #pragma unroll
        for (int nt = 0; nt < 8; nt++) {
            int col = bn + wn + nt * 8 + ec;
            float b0 = bias[col], b1 = bias[col + 1];
            #pragma unroll
            for (int mt = 0; mt < 4; mt++) {
                int row = bm + wm + mt * 16 + er;
                #pragma unroll
                for (int h = 0; h < 2; h++) {
                    float x0 = d[mt][nt][h * 2 + 0] + b0;
                    float x1 = d[mt][nt][h * 2 + 1] + b1;
                    __nv_bfloat16 h0 = __float2bfloat16(x0);
                    __nv_bfloat16 h1 = __float2bfloat16(x1);
                    __nv_bfloat16 l0 = __float2bfloat16(x0 - __bfloat162float(h0));
                    __nv_bfloat16 l1 = __float2bfloat16(x1 - __bfloat162float(h1));
                    __nv_bfloat162 hv; hv.x = h0; hv.y = h1;
                    __nv_bfloat162 lv; lv.x = l0; lv.y = l1;
                    __nv_bfloat16* base = C + (size_t)(row + h * 8) * K3 + col;
                    *reinterpret_cast<__nv_bfloat162*>(base) = hv;
                    *reinterpret_cast<__nv_bfloat162*>(base + ldc) = lv;
                    *reinterpret_cast<__nv_bfloat162*>(base + 2 * ldc) = hv;
                }
            }
        }
    }
}

// ---------------------------------------------------------------------------
// Quantum circuit kernel: one block per batch row.
// Writes probs directly as extended bf16 hi|lo|hi [row, 3*1024] for next GEMM.
// ---------------------------------------------------------------------------
__global__ __launch_bounds__(256) void circuit_kernel(
    const float* __restrict__ x,          // [4096, 1024] fp32
    const float* __restrict__ w,          // [3, 10, 3]
    __nv_bfloat16* __restrict__ out)      // [4096, 3*1024] ext bf16
{
    __shared__ float sre[1024];
    __shared__ float sim[1024];
    __shared__ float Ug[30][4];
    __shared__ float red[8];

    const int row = blockIdx.x;
    const int tid = threadIdx.x;

    if (tid < 30) {
        float phi = w[tid * 3 + 0];
        float th  = w[tid * 3 + 1];
        float om  = w[tid * 3 + 2];
        float s, c;   sincosf(0.5f * th, &s, &c);
        float sa, ca; sincosf(0.5f * (phi + om), &sa, &ca);
        float sb, cb; sincosf(0.5f * (phi - om), &sb, &cb);
        Ug[tid][0] = ca * c;
        Ug[tid][1] = sa * c;
        Ug[tid][2] = cb * s;
        Ug[tid][3] = sb * s;
    }

    float v[4];
    float ss = 0.0f;
    #pragma unroll
    for (int j = 0; j < 4; j++) {
        v[j] = x[(size_t)row * 1024 + tid + j * 256];
        ss += v[j] * v[j];
    }
    #pragma unroll
    for (int o = 16; o > 0; o >>= 1)
        ss += __shfl_xor_sync(0xFFFFFFFFu, ss, o);
    if ((tid & 31) == 0) red[tid >> 5] = ss;
    __syncthreads();
    float tot = 0.0f;
    #pragma unroll
    for (int j = 0; j < 8; j++) tot += red[j];
    float inv = rsqrtf(tot);
    #pragma unroll
    for (int j = 0; j < 4; j++) {
        sre[tid + j * 256] = v[j] * inv;
        sim[tid + j * 256] = 0.0f;
    }
    __syncthreads();

    for (int l = 0; l < 3; l++) {
        for (int q = 0; q < 10; q++) {
            const int g = l * 10 + q;
            const float Am = Ug[g][0], Bm = Ug[g][1];
            const float Cm = Ug[g][2], Dm = Ug[g][3];
            const int bit = 9 - q;
            const int mask = 1 << bit;
            #pragma unroll
            for (int p = tid; p < 512; p += 256) {
                int lo = p & (mask - 1);
                int i0 = ((p - lo) << 1) | lo;
                int i1 = i0 | mask;
                float a0r = sre[i0], a0i = sim[i0];
                float a1r = sre[i1], a1i = sim[i1];
                sre[i0] = Am * a0r + Bm * a0i - Cm * a1r + Dm * a1i;
                sim[i0] = Am * a0i - Bm * a0r - Cm * a1i - Dm * a1r;
                sre[i1] = Cm * a0r + Dm * a0i + Am * a1r - Bm * a1i;
                sim[i1] = Cm * a0i - Dm * a0r + Am * a1i + Bm * a1r;
            }
            __syncthreads();
        }
        const int r = l % 9 + 1;
        for (int q = 0; q < 10; q++) {
            const int cb = 9 - q;
            const int tb = 9 - ((q + r) % 10);
            const int cmask = 1 << cb;
            const int tmask = 1 << tb;
            const int b1 = cb < tb ? cb : tb;
            const int b2 = cb < tb ? tb : cb;
            int p  = tid;
            int lo = p & ((1 << b1) - 1);
            int mid = (p >> b1) & ((1 << (b2 - b1 - 1)) - 1);
            int hi = p >> (b2 - 1);
            int idx = (hi << (b2 + 1)) | (mid << (b1 + 1)) | lo | cmask;
            int j2 = idx | tmask;
            float tr = sre[idx], ti = sim[idx];
            sre[idx] = sre[j2]; sim[idx] = sim[j2];
            sre[j2] = tr;       sim[j2] = ti;
            __syncthreads();
        }
    }

    // probs -> extended bf16 (hi|lo|hi)
    size_t base = (size_t)row * 3072;
    #pragma unroll
    for (int j = 0; j < 4; j++) {
        int i = tid + j * 256;
        float p = sre[i] * sre[i] + sim[i] * sim[i];
        __nv_bfloat16 hi = __float2bfloat16(p);
        __nv_bfloat16 lo = __float2bfloat16(p - __bfloat162float(hi));
        out[base + i] = hi;
        out[base + 1024 + i] = lo;
        out[base + 2048 + i] = hi;
    }
}

// ---------------------------------------------------------------------------
// Final: y = |x| ; y /= rowsum(y)   x: [4096, 1024-strided], out: [4096, 1000]
// ---------------------------------------------------------------------------
__global__ __launch_bounds__(256) void abs_norm_kernel(
    const float* __restrict__ x, float* __restrict__ out)
{
    __shared__ float red[8];
    const int row = blockIdx.x;
    const int tid = threadIdx.x;

    float v[4];
    float ss = 0.0f;
    #pragma unroll
    for (int j = 0; j < 4; j++) {
        int i = tid + j * 256;
        v[j] = (i < 1000) ? fabsf(x[(size_t)row * 1024 + i]) : 0.0f;
        ss += v[j];
    }
    #pragma unroll
    for (int o = 16; o > 0; o >>= 1)
        ss += __shfl_xor_sync(0xFFFFFFFFu, ss, o);
    if ((tid & 31) == 0) red[tid >> 5] = ss;
    __syncthreads();
    float tot = 0.0f;
    #pragma unroll
    for (int j = 0; j < 8; j++) tot += red[j];
    float inv = 1.0f / tot;
    #pragma unroll
    for (int j = 0; j < 4; j++) {
        int i = tid + j * 256;
        if (i < 1000)
            out[(size_t)row * 1000 + i] = v[j] * inv;
    }
}

// ---------------------------------------------------------------------------
// Launch
// ---------------------------------------------------------------------------
extern "C" void kernel_launch(void* const* d_in, const int* in_sizes, int n_in,
                              void* d_out, int out_size)
{
    const float* inputs = (const float*)d_in[0];
    const float* wEnc   = (const float*)d_in[1];
    const float* wDec   = (const float*)d_in[2];
    const float* W0     = (const float*)d_in[3];
    const float* b0     = (const float*)d_in[4];
    const float* W1     = (const float*)d_in[5];
    const float* b1     = (const float*)d_in[6];
    const float* W2     = (const float*)d_in[7];
    const float* b2     = (const float*)d_in[8];
    const float* W3     = (const float*)d_in[9];
    const float* b3     = (const float*)d_in[10];
    float* outp = (float*)d_out;

    float *bufA = nullptr, *bufB = nullptr, *bias3 = nullptr;
    __nv_bfloat16 *actx = nullptr, *actx2 = nullptr, *w0x = nullptr,
                  *w1x = nullptr, *w2x = nullptr, *w3x = nullptr;
    cudaGetSymbolAddress((void**)&bufA, g_bufA);
    cudaGetSymbolAddress((void**)&bufB, g_bufB);
    cudaGetSymbolAddress((void**)&bias3, g_bias3);
    cudaGetSymbolAddress((void**)&actx, g_actx);
    cudaGetSymbolAddress((void**)&actx2, g_actx2);
    cudaGetSymbolAddress((void**)&w0x, g_w0x);
    cudaGetSymbolAddress((void**)&w1x, g_w1x);
    cudaGetSymbolAddress((void**)&w2x, g_w2x);
    cudaGetSymbolAddress((void**)&w3x, g_w3x);

    dim3 blk(256);
    dim3 blkg(128);
    const int GSMEM = 2 * STAGE_BYTES;   // 65536 B dynamic smem (double buffer)
    cudaFuncSetAttribute(gemm_mma,
                         cudaFuncAttributeMaxDynamicSharedMemorySize, GSMEM);

    // Weight prep (per-launch, deterministic)
    convert_weight<<<dim3(32, 32), blk>>>(W0, w0x, 1000, 1024, 1024, 1024);
    convert_weight<<<dim3(32, 64), blk>>>(W1, w1x, 1024, 2048, 1024, 2048);
    convert_weight<<<dim3(64, 32), blk>>>(W2, w2x, 2048, 1024, 2048, 1024);
    convert_weight<<<dim3(32, 32), blk>>>(W3, w3x, 1024, 1000, 1024, 1024);
    pad_bias<<<4, blk>>>(b3, bias3, 1000);

    // x = inputs @ W0 + b0                       [4096,1024] fp32
    convert_act<<<4096 * 1024 / 256, blk>>>(inputs, actx2, 1000, 1024);
    gemm_mma<<<dim3(8, 32), blkg, GSMEM>>>(3072, 1024, 0, actx2, w0x, b0, bufA);
    // x = circuit(x, wEnc) -> ext bf16
    circuit_kernel<<<4096, blk>>>(bufA, wEnc, actx2);
    // x = x @ W1 + b1                            [4096,2048] -> ext bf16
    gemm_mma<<<dim3(16, 32), blkg, GSMEM>>>(3072, 2048, 1, actx2, w1x, b1, actx);
    // x = x @ W2 + b2                            [4096,1024] fp32
    gemm_mma<<<dim3(8, 32), blkg, GSMEM>>>(6144, 1024, 0, actx, w2x, b2, bufA);
    // x = circuit(x, wDec) -> ext bf16
    circuit_kernel<<<4096, blk>>>(bufA, wDec, actx2);
    // x = x @ W3 + b3                            [4096,1024-padded] fp32
    gemm_mma<<<dim3(8, 32), blkg, GSMEM>>>(3072, 1024, 0, actx2, w3x, bias3, bufB);
    // out = |x| / rowsum(|x|)
    abs_norm_kernel<<<4096, blk>>>(bufB, outp);
}

// round 11
// speedup vs baseline: 2.9843x; 1.1794x over previous
#include <cuda_runtime.h>
#include <cuda_bf16.h>
#include <cstdint>
#include <math.h>

// ---------------------------------------------------------------------------
// Scratch (no allocs allowed -> __device__ globals)
// ---------------------------------------------------------------------------
__device__ float g_bufA[4096 * 1024];
__device__ float g_bufB[4096 * 1024];
__device__ __nv_bfloat16 g_actx[4096 * 6144];    // ext activations [M, 3*2048]
__device__ __nv_bfloat16 g_actx2[4096 * 3072];   // ext activations [M, 3*1024]
__device__ __nv_bfloat16 g_w0x[1024 * 3072];     // W^T extended [N_pad, 3*K_pad]
__device__ __nv_bfloat16 g_w1x[2048 * 3072];
__device__ __nv_bfloat16 g_w2x[1024 * 6144];
__device__ __nv_bfloat16 g_w3x[1024 * 3072];
__device__ float g_bias3[1024];

// ---------------------------------------------------------------------------
// PTX helpers (baseline sm_80+ features only: cp.async, ldmatrix, mma.sync)
// ---------------------------------------------------------------------------
__device__ __forceinline__ uint32_t smem_u32(const void* p) {
    uint32_t a;
    asm("{ .reg .u64 t; cvta.to.shared.u64 t, %1; cvt.u32.u64 %0, t; }"
        : "=r"(a) : "l"(p));
    return a;
}

#define CP_ASYNC16(dst_u32, src_ptr)                                          \
    asm volatile("cp.async.cg.shared.global [%0], [%1], 16;"                  \
                 :: "r"(dst_u32), "l"(src_ptr))
#define CP_COMMIT() asm volatile("cp.async.commit_group;" ::: "memory")
#define CP_WAIT(n)  asm volatile("cp.async.wait_group %0;" :: "n"(n) : "memory")

#define LDSM_X4(r0, r1, r2, r3, addr)                                         \
    asm volatile("ldmatrix.sync.aligned.m8n8.x4.shared.b16 {%0,%1,%2,%3}, [%4];" \
                 : "=r"(r0), "=r"(r1), "=r"(r2), "=r"(r3) : "r"(addr))

#define MMA_16816(d, a, b)                                                    \
    asm volatile(                                                             \
        "mma.sync.aligned.m16n8k16.row.col.f32.bf16.bf16.f32 "                \
        "{%0,%1,%2,%3}, {%4,%5,%6,%7}, {%8,%9}, {%0,%1,%2,%3};"               \
        : "+f"((d)[0]), "+f"((d)[1]), "+f"((d)[2]), "+f"((d)[3])              \
        : "r"((a)[0]), "r"((a)[1]), "r"((a)[2]), "r"((a)[3]),                 \
          "r"((b)[0]), "r"((b)[1]))

// ---------------------------------------------------------------------------
// Circuit schedule table (host-computed, structure is weight-independent).
// For each of the 30 rotations: m = physical pair XOR mask (column of P),
// r = side-selector row (row of P^-1). fcol = final permutation columns.
// ---------------------------------------------------------------------------
struct CircTab {
    unsigned short m[30];
    unsigned short r[30];
    unsigned short fcol[10];
};

// ---------------------------------------------------------------------------
// Conversion kernels: fp32 -> extended bf16 (hi|lo|hi for A, hi|hi|lo for B)
// ---------------------------------------------------------------------------
__global__ __launch_bounds__(256) void convert_act(
    const float* __restrict__ in, __nv_bfloat16* __restrict__ out,
    int K_in, int K_pad)
{
    int idx = blockIdx.x * 256 + threadIdx.x;     // over rows * K_pad
    int r = idx / K_pad;
    int k = idx - r * K_pad;
    float x = (k < K_in) ? in[(size_t)r * K_in + k] : 0.0f;
    __nv_bfloat16 hi = __float2bfloat16(x);
    __nv_bfloat16 lo = __float2bfloat16(x - __bfloat162float(hi));
    size_t base = (size_t)r * 3 * K_pad;
    out[base + k] = hi;                 // hi block
    out[base + K_pad + k] = lo;         // lo block  (pairs with B's hi)
    out[base + 2 * K_pad + k] = hi;     // hi block  (pairs with B's lo)
}

// W [K_in, N_in] row-major  ->  out [N_pad, 3*K_pad] (transposed, hi|hi|lo)
__global__ __launch_bounds__(256) void convert_weight(
    const float* __restrict__ W, __nv_bfloat16* __restrict__ out,
    int K_in, int N_in, int K_pad, int N_pad)
{
    __shared__ float t[32][33];
    int k0 = blockIdx.x * 32, n0 = blockIdx.y * 32;
    int tx = threadIdx.x & 31, ty = threadIdx.x >> 5;   // ty 0..7
    #pragma unroll
    for (int i = 0; i < 32; i += 8) {
        int k = k0 + ty + i, n = n0 + tx;
        t[ty + i][tx] = (k < K_in && n < N_in) ? W[(size_t)k * N_in + n] : 0.0f;
    }
    __syncthreads();
    size_t K3 = 3 * (size_t)K_pad;
    #pragma unroll
    for (int i = 0; i < 32; i += 8) {
        int n = n0 + ty + i, k = k0 + tx;
        if (n < N_pad && k < K_pad) {
            float x = t[tx][ty + i];
            __nv_bfloat16 hi = __float2bfloat16(x);
            __nv_bfloat16 lo = __float2bfloat16(x - __bfloat162float(hi));
            __nv_bfloat16* row = out + (size_t)n * K3;
            row[k] = hi;
            row[K_pad + k] = hi;
            row[2 * K_pad + k] = lo;
        }
    }
}

__global__ void pad_bias(const float* __restrict__ b, float* __restrict__ out,
                         int n_in)
{
    int i = blockIdx.x * 256 + threadIdx.x;
    out[i] = (i < n_in) ? b[i] : 0.0f;
}

// ---------------------------------------------------------------------------
// mma.sync GEMM: C[M,N] = A'[M,Kx] @ B'[N,Kx]^T + bias  (bf16 in)
// CTA tile 128x128, BK=64 (128B rows, XOR-swizzled), cp.async double buffer.
// 4 warps (128 threads), warp tile 64x64. grid = (N/128, M/128).
// mode 0: write fp32 C (ldc stride). mode 1: write extended bf16 hi|lo|hi
//         to C as [row, 3*ldc] (feeds the next GEMM directly).
// ---------------------------------------------------------------------------
#define TILE_BYTES 16384          // 128 rows * 128 B
#define STAGE_BYTES (2 * TILE_BYTES)

__global__ __launch_bounds__(128, 2) void gemm_mma(
    int Kx, int ldc, int mode,
    const __nv_bfloat16* __restrict__ A, const __nv_bfloat16* __restrict__ B,
    const float* __restrict__ bias, void* __restrict__ Cv)
{
    extern __shared__ char smem[];
    uint32_t sb = smem_u32(smem);

    const int tid = threadIdx.x;
    const int wid = tid >> 5, lane = tid & 31;
    const int bm = blockIdx.y * 128, bn = blockIdx.x * 128;
    const int wm = (wid & 1) * 64;       // warp M offset in tile
    const int wn = (wid >> 1) * 64;      // warp N offset in tile

    float d[4][8][4];
    #pragma unroll
    for (int mt = 0; mt < 4; mt++)
        #pragma unroll
        for (int nt = 0; nt < 8; nt++)
            #pragma unroll
            for (int e = 0; e < 4; e++)
                d[mt][nt][e] = 0.0f;

    const int nch = Kx >> 6;

    // ---- loader (cp.async): 32KB per chunk over 128 threads ----
    auto load_chunk = [&](int ch, int buf) {
        const int kc = ch << 6;
        uint32_t sA = sb + buf * STAGE_BYTES;
        uint32_t sB = sA + TILE_BYTES;
        #pragma unroll
        for (int it = 0; it < 8; it++) {
            int f = tid + it * 128;            // 0..1023
            int r = f >> 3, c16 = f & 7;
            uint32_t off = (uint32_t)(r * 128 + c16 * 16);
            off ^= (off >> 3) & 0x70;
            const __nv_bfloat16* srcA = A + (size_t)(bm + r) * Kx + kc + c16 * 8;
            const __nv_bfloat16* srcB = B + (size_t)(bn + r) * Kx + kc + c16 * 8;
            CP_ASYNC16(sA + off, srcA);
            CP_ASYNC16(sB + off, srcB);
        }
    };

    load_chunk(0, 0);
    CP_COMMIT();

    for (int ch = 0; ch < nch; ch++) {
        const int cur = ch & 1;
        if (ch + 1 < nch) {
            load_chunk(ch + 1, cur ^ 1);
            CP_COMMIT();
            CP_WAIT(1);
        } else {
            CP_WAIT(0);
        }
        __syncthreads();

        uint32_t sA = sb + cur * STAGE_BYTES;
        uint32_t sB = sA + TILE_BYTES;

        #pragma unroll
        for (int s = 0; s < 4; s++) {          // 4 k16-steps in BK=64
            uint32_t a[4][4];
            uint32_t b[8][2];
            // A fragments: 4 m-tiles of 16 rows
            #pragma unroll
            for (int mt = 0; mt < 4; mt++) {
                int row = wm + mt * 16 + (lane & 15);
                int colb = s * 32 + ((lane >> 4) & 1) * 16;
                uint32_t off = (uint32_t)(row * 128 + colb);
                off ^= (off >> 3) & 0x70;
                LDSM_X4(a[mt][0], a[mt][1], a[mt][2], a[mt][3], sA + off);
            }
            // B fragments: 4 x ldmatrix.x4 cover 8 n-tiles of 8 cols
            #pragma unroll
            for (int nt2 = 0; nt2 < 4; nt2++) {
                int row = wn + nt2 * 16 + ((lane >> 4) & 1) * 8 + (lane & 7);
                int colb = s * 32 + ((lane >> 3) & 1) * 16;
                uint32_t off = (uint32_t)(row * 128 + colb);
                off ^= (off >> 3) & 0x70;
                uint32_t r0, r1, r2, r3;
                LDSM_X4(r0, r1, r2, r3, sB + off);
                b[nt2 * 2 + 0][0] = r0; b[nt2 * 2 + 0][1] = r1;
                b[nt2 * 2 + 1][0] = r2; b[nt2 * 2 + 1][1] = r3;
            }
            #pragma unroll
            for (int mt = 0; mt < 4; mt++)
                #pragma unroll
                for (int nt = 0; nt < 8; nt++)
                    MMA_16816(d[mt][nt], a[mt], b[nt]);
        }
        __syncthreads();
    }

    // Epilogue. Fragment layout: d0:(r,c) d1:(r,c+1) d2:(r+8,c) d3:(r+8,c+1)
    // with r = lane>>2, c = (lane&3)*2.
    const int er = lane >> 2;
    const int ec = (lane & 3) * 2;
    if (mode == 0) {
        float* C = (float*)Cv;
        #pragma unroll
        for (int nt = 0; nt < 8; nt++) {
            int col = bn + wn + nt * 8 + ec;
            float b0 = bias[col], b1 = bias[col + 1];
            #pragma unroll
            for (int mt = 0; mt < 4; mt++) {
                int row = bm + wm + mt * 16 + er;
                float2 v0 = make_float2(d[mt][nt][0] + b0, d[mt][nt][1] + b1);
                float2 v1 = make_float2(d[mt][nt][2] + b0, d[mt][nt][3] + b1);
                *reinterpret_cast<float2*>(C + (size_t)row * ldc + col) = v0;
                *reinterpret_cast<float2*>(C + (size_t)(row + 8) * ldc + col) = v1;
            }
        }
    } else {
        // Extended bf16 output: [row, 3*ldc] = hi | lo | hi
        __nv_bfloat16* C = (__nv_bfloat16*)Cv;
        const size_t K3 = 3 * (size_t)ldc;
        #pragma unroll
        for (int nt = 0; nt < 8; nt++) {
            int col = bn + wn + nt * 8 + ec;
            float b0 = bias[col], b1 = bias[col + 1];
            #pragma unroll
            for (int mt = 0; mt < 4; mt++) {
                int row = bm + wm + mt * 16 + er;
                #pragma unroll
                for (int h = 0; h < 2; h++) {
                    float x0 = d[mt][nt][h * 2 + 0] + b0;
                    float x1 = d[mt][nt][h * 2 + 1] + b1;
                    __nv_bfloat16 h0 = __float2bfloat16(x0);
                    __nv_bfloat16 h1 = __float2bfloat16(x1);
                    __nv_bfloat16 l0 = __float2bfloat16(x0 - __bfloat162float(h0));
                    __nv_bfloat16 l1 = __float2bfloat16(x1 - __bfloat162float(h1));
                    __nv_bfloat162 hv; hv.x = h0; hv.y = h1;
                    __nv_bfloat162 lv; lv.x = l0; lv.y = l1;
                    __nv_bfloat16* base = C + (size_t)(row + h * 8) * K3 + col;
                    *reinterpret_cast<__nv_bfloat162*>(base) = hv;
                    *reinterpret_cast<__nv_bfloat162*>(base + ldc) = lv;
                    *reinterpret_cast<__nv_bfloat162*>(base + 2 * ldc) = hv;
                }
            }
        }
    }
}

// ---------------------------------------------------------------------------
// Quantum circuit kernel: one block per batch row.
// CNOTs are tracked as a GF(2) linear index map (host-computed CircTab) —
// zero data movement, zero syncs. Each rotation g updates pairs (y, y^m[g])
// where side selection uses parity of <r[g], y>. 30 syncthreads total.
// Writes probs (at logical index via fcol permutation) as ext bf16 hi|lo|hi.
// ---------------------------------------------------------------------------
__global__ __launch_bounds__(256) void circuit_kernel(
    const float* __restrict__ x,          // [4096, 1024] fp32
    const float* __restrict__ w,          // [3, 10, 3]
    CircTab tab,
    __nv_bfloat16* __restrict__ out)      // [4096, 3*1024] ext bf16
{
    __shared__ float sre[1024];
    __shared__ float sim[1024];
    __shared__ float Ug[30][4];
    __shared__ float red[8];

    const int row = blockIdx.x;
    const int tid = threadIdx.x;

    if (tid < 30) {
        float phi = w[tid * 3 + 0];
        float th  = w[tid * 3 + 1];
        float om  = w[tid * 3 + 2];
        float s, c;   sincosf(0.5f * th, &s, &c);
        float sa, ca; sincosf(0.5f * (phi + om), &sa, &ca);
        float sb, cb; sincosf(0.5f * (phi - om), &sb, &cb);
        Ug[tid][0] = ca * c;
        Ug[tid][1] = sa * c;
        Ug[tid][2] = cb * s;
        Ug[tid][3] = sb * s;
    }

    float v[4];
    float ss = 0.0f;
    #pragma unroll
    for (int j = 0; j < 4; j++) {
        v[j] = x[(size_t)row * 1024 + tid + j * 256];
        ss += v[j] * v[j];
    }
    #pragma unroll
    for (int o = 16; o > 0; o >>= 1)
        ss += __shfl_xor_sync(0xFFFFFFFFu, ss, o);
    if ((tid & 31) == 0) red[tid >> 5] = ss;
    __syncthreads();
    float tot = 0.0f;
    #pragma unroll
    for (int j = 0; j < 8; j++) tot += red[j];
    float inv = rsqrtf(tot);
    #pragma unroll
    for (int j = 0; j < 4; j++) {
        sre[tid + j * 256] = v[j] * inv;
        sim[tid + j * 256] = 0.0f;
    }
    __syncthreads();

    // 30 rotations; CNOTs are folded into the (m, r) masks.
    for (int g = 0; g < 30; g++) {
        const float Am = Ug[g][0], Bm = Ug[g][1];
        const float Cm = Ug[g][2], Dm = Ug[g][3];
        const unsigned m  = tab.m[g];
        const unsigned rr = tab.r[g];
        const unsigned pbm = rr & (0u - rr);       // lowest set bit of rr
        const unsigned lomask = pbm - 1;
        #pragma unroll
        for (int it = 0; it < 2; it++) {
            unsigned p = (unsigned)tid + it * 256; // 0..511
            unsigned lo = p & lomask;
            unsigned y0 = ((p ^ lo) << 1) | lo;    // insert 0 at pivot bit
            unsigned par = __popc(y0 & rr) & 1;
            unsigned i0 = y0 | (par ? pbm : 0u);   // <rr, i0> = 0  (logical bit = 0)
            unsigned i1 = i0 ^ m;                  // logical bit = 1 partner
            float a0r = sre[i0], a0i = sim[i0];
            float a1r = sre[i1], a1i = sim[i1];
            sre[i0] = Am * a0r + Bm * a0i - Cm * a1r + Dm * a1i;
            sim[i0] = Am * a0i - Bm * a0r - Cm * a1i - Dm * a1r;
            sre[i1] = Cm * a0r + Dm * a0i + Am * a1r - Bm * a1i;
            sim[i1] = Cm * a0i - Dm * a0r + Am * a1i + Bm * a1r;
        }
        __syncthreads();
    }

    // probs at logical index b live at physical P(b) -> ext bf16 (hi|lo|hi)
    size_t base = (size_t)row * 3072;
    #pragma unroll
    for (int j = 0; j < 4; j++) {
        int b = tid + j * 256;
        unsigned phys = 0;
        #pragma unroll
        for (int k2 = 0; k2 < 10; k2++)
            if ((b >> k2) & 1) phys ^= tab.fcol[k2];
        float pre = sre[phys], pim = sim[phys];
        float p = pre * pre + pim * pim;
        __nv_bfloat16 hi = __float2bfloat16(p);
        __nv_bfloat16 lo = __float2bfloat16(p - __bfloat162float(hi));
        out[base + b] = hi;
        out[base + 1024 + b] = lo;
        out[base + 2048 + b] = hi;
    }
}

// ---------------------------------------------------------------------------
// Final: y = |x| ; y /= rowsum(y)   x: [4096, 1024-strided], out: [4096, 1000]
// ---------------------------------------------------------------------------
__global__ __launch_bounds__(256) void abs_norm_kernel(
    const float* __restrict__ x, float* __restrict__ out)
{
    __shared__ float red[8];
    const int row = blockIdx.x;
    const int tid = threadIdx.x;

    float v[4];
    float ss = 0.0f;
    #pragma unroll
    for (int j = 0; j < 4; j++) {
        int i = tid + j * 256;
        v[j] = (i < 1000) ? fabsf(x[(size_t)row * 1024 + i]) : 0.0f;
        ss += v[j];
    }
    #pragma unroll
    for (int o = 16; o > 0; o >>= 1)
        ss += __shfl_xor_sync(0xFFFFFFFFu, ss, o);
    if ((tid & 31) == 0) red[tid >> 5] = ss;
    __syncthreads();
    float tot = 0.0f;
    #pragma unroll
    for (int j = 0; j < 8; j++) tot += red[j];
    float inv = 1.0f / tot;
    #pragma unroll
    for (int j = 0; j < 4; j++) {
        int i = tid + j * 256;
        if (i < 1000)
            out[(size_t)row * 1000 + i] = v[j] * inv;
    }
}

// ---------------------------------------------------------------------------
// Host: compute circuit schedule (structure-only, weight-independent).
// P tracks the accumulated CNOT linear map; pr tracks rows of P^-1.
// ---------------------------------------------------------------------------
static CircTab make_circ_tab()
{
    unsigned pc[10], pr[10];
    for (int j = 0; j < 10; j++) { pc[j] = 1u << j; pr[j] = 1u << j; }
    CircTab t;
    for (int l = 0; l < 3; l++) {
        for (int q = 0; q < 10; q++) {
            int g = l * 10 + q, b = 9 - q;          // wire q <-> bit 9-q
            t.m[g] = (unsigned short)pc[b];
            t.r[g] = (unsigned short)pr[b];
        }
        int rr = l % 9 + 1;
        for (int q = 0; q < 10; q++) {
            int c = 9 - q;                           // control bit
            int tt = 9 - ((q + rr) % 10);            // target bit
            pc[c] ^= pc[tt];                         // P' = P * C (column op)
            pr[tt] ^= pr[c];                         // P'^-1 = C * P^-1 (row op)
        }
    }
    for (int j = 0; j < 10; j++) t.fcol[j] = (unsigned short)pc[j];
    return t;
}

// ---------------------------------------------------------------------------
// Launch
// ---------------------------------------------------------------------------
extern "C" void kernel_launch(void* const* d_in, const int* in_sizes, int n_in,
                              void* d_out, int out_size)
{
    const float* inputs = (const float*)d_in[0];
    const float* wEnc   = (const float*)d_in[1];
    const float* wDec   = (const float*)d_in[2];
    const float* W0     = (const float*)d_in[3];
    const float* b0     = (const float*)d_in[4];
    const float* W1     = (const float*)d_in[5];
    const float* b1     = (const float*)d_in[6];
    const float* W2     = (const float*)d_in[7];
    const float* b2     = (const float*)d_in[8];
    const float* W3     = (const float*)d_in[9];
    const float* b3     = (const float*)d_in[10];
    float* outp = (float*)d_out;

    float *bufA = nullptr, *bufB = nullptr, *bias3 = nullptr;
    __nv_bfloat16 *actx = nullptr, *actx2 = nullptr, *w0x = nullptr,
                  *w1x = nullptr, *w2x = nullptr, *w3x = nullptr;
    cudaGetSymbolAddress((void**)&bufA, g_bufA);
    cudaGetSymbolAddress((void**)&bufB, g_bufB);
    cudaGetSymbolAddress((void**)&bias3, g_bias3);
    cudaGetSymbolAddress((void**)&actx, g_actx);
    cudaGetSymbolAddress((void**)&actx2, g_actx2);
    cudaGetSymbolAddress((void**)&w0x, g_w0x);
    cudaGetSymbolAddress((void**)&w1x, g_w1x);
    cudaGetSymbolAddress((void**)&w2x, g_w2x);
    cudaGetSymbolAddress((void**)&w3x, g_w3x);

    const CircTab tab = make_circ_tab();

    dim3 blk(256);
    dim3 blkg(128);
    const int GSMEM = 2 * STAGE_BYTES;   // 65536 B dynamic smem (double buffer)
    cudaFuncSetAttribute(gemm_mma,
                         cudaFuncAttributeMaxDynamicSharedMemorySize, GSMEM);

    // Weight prep (per-launch, deterministic)
    convert_weight<<<dim3(32, 32), blk>>>(W0, w0x, 1000, 1024, 1024, 1024);
    convert_weight<<<dim3(32, 64), blk>>>(W1, w1x, 1024, 2048, 1024, 2048);
    convert_weight<<<dim3(64, 32), blk>>>(W2, w2x, 2048, 1024, 2048, 1024);
    convert_weight<<<dim3(32, 32), blk>>>(W3, w3x, 1024, 1000, 1024, 1024);
    pad_bias<<<4, blk>>>(b3, bias3, 1000);

    // x = inputs @ W0 + b0                       [4096,1024] fp32
    convert_act<<<4096 * 1024 / 256, blk>>>(inputs, actx2, 1000, 1024);
    gemm_mma<<<dim3(8, 32), blkg, GSMEM>>>(3072, 1024, 0, actx2, w0x, b0, bufA);
    // x = circuit(x, wEnc) -> ext bf16
    circuit_kernel<<<4096, blk>>>(bufA, wEnc, tab, actx2);
    // x = x @ W1 + b1                            [4096,2048] -> ext bf16
    gemm_mma<<<dim3(16, 32), blkg, GSMEM>>>(3072, 2048, 1, actx2, w1x, b1, actx);
    // x = x @ W2 + b2                            [4096,1024] fp32
    gemm_mma<<<dim3(8, 32), blkg, GSMEM>>>(6144, 1024, 0, actx, w2x, b2, bufA);
    // x = circuit(x, wDec) -> ext bf16
    circuit_kernel<<<4096, blk>>>(bufA, wDec, tab, actx2);
    // x = x @ W3 + b3                            [4096,1024-padded] fp32
    gemm_mma<<<dim3(8, 32), blkg, GSMEM>>>(3072, 1024, 0, actx2, w3x, bias3, bufB);
    // out = |x| / rowsum(|x|)
    abs_norm_kernel<<<4096, blk>>>(bufB, outp);
}

// round 12
// speedup vs baseline: 3.1750x; 1.0639x over previous
#include <cuda_runtime.h>
#include <cuda_bf16.h>
#include <cstdint>
#include <math.h>

// ---------------------------------------------------------------------------
// Scratch (no allocs allowed -> __device__ globals)
// ---------------------------------------------------------------------------
__device__ float g_bufA[4096 * 1024];
__device__ float g_bufB[4096 * 1024];
__device__ __nv_bfloat16 g_actx2[4096 * 3072];   // ext activations [M, 3*1024]
__device__ __nv_bfloat16 g_w0x[1024 * 3072];     // W^T extended [N_pad, 3*K_pad]
__device__ __nv_bfloat16 g_w1e[1024 * 6144];     // W1 ext (act-style) [1024, 3*2048]
__device__ __nv_bfloat16 g_w2x[1024 * 6144];     // W2^T ext [1024, 3*2048]
__device__ __nv_bfloat16 g_w3x[1024 * 3072];
__device__ __nv_bfloat16 g_wcx[1024 * 3072];     // Wc^T ext [1024, 3*1024]
__device__ float g_wcPart[4 * 1024 * 1024];      // split-K partials for Wc
__device__ float g_bias3[1024];
__device__ float g_biasC[1024];

// ---------------------------------------------------------------------------
// PTX helpers (baseline sm_80+ features only: cp.async, ldmatrix, mma.sync)
// ---------------------------------------------------------------------------
__device__ __forceinline__ uint32_t smem_u32(const void* p) {
    uint32_t a;
    asm("{ .reg .u64 t; cvta.to.shared.u64 t, %1; cvt.u32.u64 %0, t; }"
        : "=r"(a) : "l"(p));
    return a;
}

#define CP_ASYNC16(dst_u32, src_ptr)                                          \
    asm volatile("cp.async.cg.shared.global [%0], [%1], 16;"                  \
                 :: "r"(dst_u32), "l"(src_ptr))
#define CP_COMMIT() asm volatile("cp.async.commit_group;" ::: "memory")
#define CP_WAIT(n)  asm volatile("cp.async.wait_group %0;" :: "n"(n) : "memory")

#define LDSM_X4(r0, r1, r2, r3, addr)                                         \
    asm volatile("ldmatrix.sync.aligned.m8n8.x4.shared.b16 {%0,%1,%2,%3}, [%4];" \
                 : "=r"(r0), "=r"(r1), "=r"(r2), "=r"(r3) : "r"(addr))

#define MMA_16816(d, a, b)                                                    \
    asm volatile(                                                             \
        "mma.sync.aligned.m16n8k16.row.col.f32.bf16.bf16.f32 "                \
        "{%0,%1,%2,%3}, {%4,%5,%6,%7}, {%8,%9}, {%0,%1,%2,%3};"               \
        : "+f"((d)[0]), "+f"((d)[1]), "+f"((d)[2]), "+f"((d)[3])              \
        : "r"((a)[0]), "r"((a)[1]), "r"((a)[2]), "r"((a)[3]),                 \
          "r"((b)[0]), "r"((b)[1]))

// ---------------------------------------------------------------------------
// Circuit schedule table (host-computed, structure is weight-independent).
// ---------------------------------------------------------------------------
struct CircTab {
    unsigned short m[30];
    unsigned short r[30];
    unsigned short fcol[10];
};

// ---------------------------------------------------------------------------
// Conversion kernels: fp32 -> extended bf16 (hi|lo|hi for A, hi|hi|lo for B)
// ---------------------------------------------------------------------------
__global__ __launch_bounds__(256) void convert_act(
    const float* __restrict__ in, __nv_bfloat16* __restrict__ out,
    int K_in, int K_pad)
{
    int idx = blockIdx.x * 256 + threadIdx.x;     // over rows * K_pad
    int r = idx / K_pad;
    int k = idx - r * K_pad;
    float x = (k < K_in) ? in[(size_t)r * K_in + k] : 0.0f;
    __nv_bfloat16 hi = __float2bfloat16(x);
    __nv_bfloat16 lo = __float2bfloat16(x - __bfloat162float(hi));
    size_t base = (size_t)r * 3 * K_pad;
    out[base + k] = hi;                 // hi block
    out[base + K_pad + k] = lo;         // lo block  (pairs with B's hi)
    out[base + 2 * K_pad + k] = hi;     // hi block  (pairs with B's lo)
}

// W [K_in, N_in] row-major  ->  out [N_pad, 3*K_pad] (transposed, hi|hi|lo)
__global__ __launch_bounds__(256) void convert_weight(
    const float* __restrict__ W, __nv_bfloat16* __restrict__ out,
    int K_in, int N_in, int K_pad, int N_pad)
{
    __shared__ float t[32][33];
    int k0 = blockIdx.x * 32, n0 = blockIdx.y * 32;
    int tx = threadIdx.x & 31, ty = threadIdx.x >> 5;   // ty 0..7
    #pragma unroll
    for (int i = 0; i < 32; i += 8) {
        int k = k0 + ty + i, n = n0 + tx;
        t[ty + i][tx] = (k < K_in && n < N_in) ? W[(size_t)k * N_in + n] : 0.0f;
    }
    __syncthreads();
    size_t K3 = 3 * (size_t)K_pad;
    #pragma unroll
    for (int i = 0; i < 32; i += 8) {
        int n = n0 + ty + i, k = k0 + tx;
        if (n < N_pad && k < K_pad) {
            float x = t[tx][ty + i];
            __nv_bfloat16 hi = __float2bfloat16(x);
            __nv_bfloat16 lo = __float2bfloat16(x - __bfloat162float(hi));
            __nv_bfloat16* row = out + (size_t)n * K3;
            row[k] = hi;
            row[K_pad + k] = hi;
            row[2 * K_pad + k] = lo;
        }
    }
}

__global__ void pad_bias(const float* __restrict__ b, float* __restrict__ out,
                         int n_in)
{
    int i = blockIdx.x * 256 + threadIdx.x;
    out[i] = (i < n_in) ? b[i] : 0.0f;
}

// bc[j] = sum_k b1[k] * W2[k][j] + b2[j]     (W2: [2048, 1024])
__global__ __launch_bounds__(256) void bias_compose(
    const float* __restrict__ b1, const float* __restrict__ W2,
    const float* __restrict__ b2, float* __restrict__ out)
{
    int j = blockIdx.x * 256 + threadIdx.x;   // 0..1023
    float s0 = 0.0f, s1 = 0.0f, s2 = 0.0f, s3 = 0.0f;
    #pragma unroll 4
    for (int k = 0; k < 2048; k += 4) {
        s0 += b1[k + 0] * W2[(size_t)(k + 0) * 1024 + j];
        s1 += b1[k + 1] * W2[(size_t)(k + 1) * 1024 + j];
        s2 += b1[k + 2] * W2[(size_t)(k + 2) * 1024 + j];
        s3 += b1[k + 3] * W2[(size_t)(k + 3) * 1024 + j];
    }
    out[j] = (s0 + s1) + (s2 + s3) + b2[j];
}

// Sum the 4 split-K partial planes (deterministic, no atomics)
__global__ __launch_bounds__(256) void reduce4(
    const float* __restrict__ p, float* __restrict__ out)
{
    int i = blockIdx.x * 256 + threadIdx.x;   // 0..1M-1
    const int PL = 1024 * 1024;
    out[i] = (p[i] + p[i + PL]) + (p[i + 2 * PL] + p[i + 3 * PL]);
}

// ---------------------------------------------------------------------------
// mma.sync GEMM: C[M,N] = A'[M,*] @ B'[N,*]^T (+ bias)   (bf16 in)
// CTA tile 128x128, BK=64 (128B rows, XOR-swizzled), cp.async double buffer.
// 4 warps (128 threads), warp tile 64x64. grid = (N/128, M/128, Ksplit).
// Kx = K-length this CTA sweeps; lda = row stride (elements) of A and B;
// blockIdx.z offsets K by z*Kx (split-K).
// mode 0: write fp32 C (+bias). mode 2: write fp32 partial plane z (no bias).
// ---------------------------------------------------------------------------
#define TILE_BYTES 16384          // 128 rows * 128 B
#define STAGE_BYTES (2 * TILE_BYTES)

__global__ __launch_bounds__(128, 2) void gemm_mma(
    int Kx, int lda, int ldc, int mode,
    const __nv_bfloat16* __restrict__ A, const __nv_bfloat16* __restrict__ B,
    const float* __restrict__ bias, float* __restrict__ C)
{
    extern __shared__ char smem[];
    uint32_t sb = smem_u32(smem);

    const int tid = threadIdx.x;
    const int wid = tid >> 5, lane = tid & 31;
    const int bm = blockIdx.y * 128, bn = blockIdx.x * 128;
    const int koff = blockIdx.z * Kx;
    const int wm = (wid & 1) * 64;       // warp M offset in tile
    const int wn = (wid >> 1) * 64;      // warp N offset in tile

    float d[4][8][4];
    #pragma unroll
    for (int mt = 0; mt < 4; mt++)
        #pragma unroll
        for (int nt = 0; nt < 8; nt++)
            #pragma unroll
            for (int e = 0; e < 4; e++)
                d[mt][nt][e] = 0.0f;

    const int nch = Kx >> 6;

    // ---- loader (cp.async): 32KB per chunk over 128 threads ----
    auto load_chunk = [&](int ch, int buf) {
        const int kc = koff + (ch << 6);
        uint32_t sA = sb + buf * STAGE_BYTES;
        uint32_t sB = sA + TILE_BYTES;
        #pragma unroll
        for (int it = 0; it < 8; it++) {
            int f = tid + it * 128;            // 0..1023
            int r = f >> 3, c16 = f & 7;
            uint32_t off = (uint32_t)(r * 128 + c16 * 16);
            off ^= (off >> 3) & 0x70;
            const __nv_bfloat16* srcA = A + (size_t)(bm + r) * lda + kc + c16 * 8;
            const __nv_bfloat16* srcB = B + (size_t)(bn + r) * lda + kc + c16 * 8;
            CP_ASYNC16(sA + off, srcA);
            CP_ASYNC16(sB + off, srcB);
        }
    };

    load_chunk(0, 0);
    CP_COMMIT();

    for (int ch = 0; ch < nch; ch++) {
        const int cur = ch & 1;
        if (ch + 1 < nch) {
            load_chunk(ch + 1, cur ^ 1);
            CP_COMMIT();
            CP_WAIT(1);
        } else {
            CP_WAIT(0);
        }
        __syncthreads();

        uint32_t sA = sb + cur * STAGE_BYTES;
        uint32_t sB = sA + TILE_BYTES;

        #pragma unroll
        for (int s = 0; s < 4; s++) {          // 4 k16-steps in BK=64
            uint32_t a[4][4];
            uint32_t b[8][2];
            // A fragments: 4 m-tiles of 16 rows
            #pragma unroll
            for (int mt = 0; mt < 4; mt++) {
                int row = wm + mt * 16 + (lane & 15);
                int colb = s * 32 + ((lane >> 4) & 1) * 16;
                uint32_t off = (uint32_t)(row * 128 + colb);
                off ^= (off >> 3) & 0x70;
                LDSM_X4(a[mt][0], a[mt][1], a[mt][2], a[mt][3], sA + off);
            }
            // B fragments: 4 x ldmatrix.x4 cover 8 n-tiles of 8 cols
            #pragma unroll
            for (int nt2 = 0; nt2 < 4; nt2++) {
                int row = wn + nt2 * 16 + ((lane >> 4) & 1) * 8 + (lane & 7);
                int colb = s * 32 + ((lane >> 3) & 1) * 16;
                uint32_t off = (uint32_t)(row * 128 + colb);
                off ^= (off >> 3) & 0x70;
                uint32_t r0, r1, r2, r3;
                LDSM_X4(r0, r1, r2, r3, sB + off);
                b[nt2 * 2 + 0][0] = r0; b[nt2 * 2 + 0][1] = r1;
                b[nt2 * 2 + 1][0] = r2; b[nt2 * 2 + 1][1] = r3;
            }
            #pragma unroll
            for (int mt = 0; mt < 4; mt++)
                #pragma unroll
                for (int nt = 0; nt < 8; nt++)
                    MMA_16816(d[mt][nt], a[mt], b[nt]);
        }
        __syncthreads();
    }

    // Epilogue. Fragment layout: d0:(r,c) d1:(r,c+1) d2:(r+8,c) d3:(r+8,c+1)
    // with r = lane>>2, c = (lane&3)*2.
    const int er = lane >> 2;
    const int ec = (lane & 3) * 2;
    float* Co = C;
    if (mode == 2) {
        size_t plane = (size_t)(gridDim.x * 128) * (size_t)(gridDim.y * 128);
        Co += (size_t)blockIdx.z * plane;
    }
    #pragma unroll
    for (int nt = 0; nt < 8; nt++) {
        int col = bn + wn + nt * 8 + ec;
        float b0 = 0.0f, b1 = 0.0f;
        if (mode == 0) { b0 = bias[col]; b1 = bias[col + 1]; }
        #pragma unroll
        for (int mt = 0; mt < 4; mt++) {
            int row = bm + wm + mt * 16 + er;
            float2 v0 = make_float2(d[mt][nt][0] + b0, d[mt][nt][1] + b1);
            float2 v1 = make_float2(d[mt][nt][2] + b0, d[mt][nt][3] + b1);
            *reinterpret_cast<float2*>(Co + (size_t)row * ldc + col) = v0;
            *reinterpret_cast<float2*>(Co + (size_t)(row + 8) * ldc + col) = v1;
        }
    }
}

// ---------------------------------------------------------------------------
// Quantum circuit kernel: one block per batch row. CNOTs tracked as GF(2)
// linear map (CircTab). 30 pair-rotations, 30 syncs, no swaps.
// Writes probs as extended bf16 hi|lo|hi for the next GEMM.
// ---------------------------------------------------------------------------
__global__ __launch_bounds__(256) void circuit_kernel(
    const float* __restrict__ x,          // [4096, 1024] fp32
    const float* __restrict__ w,          // [3, 10, 3]
    CircTab tab,
    __nv_bfloat16* __restrict__ out)      // [4096, 3*1024] ext bf16
{
    __shared__ float sre[1024];
    __shared__ float sim[1024];
    __shared__ float Ug[30][4];
    __shared__ float red[8];

    const int row = blockIdx.x;
    const int tid = threadIdx.x;

    if (tid < 30) {
        float phi = w[tid * 3 + 0];
        float th  = w[tid * 3 + 1];
        float om  = w[tid * 3 + 2];
        float s, c;   sincosf(0.5f * th, &s, &c);
        float sa, ca; sincosf(0.5f * (phi + om), &sa, &ca);
        float sb, cb; sincosf(0.5f * (phi - om), &sb, &cb);
        Ug[tid][0] = ca * c;
        Ug[tid][1] = sa * c;
        Ug[tid][2] = cb * s;
        Ug[tid][3] = sb * s;
    }

    float v[4];
    float ss = 0.0f;
    #pragma unroll
    for (int j = 0; j < 4; j++) {
        v[j] = x[(size_t)row * 1024 + tid + j * 256];
        ss += v[j] * v[j];
    }
    #pragma unroll
    for (int o = 16; o > 0; o >>= 1)
        ss += __shfl_xor_sync(0xFFFFFFFFu, ss, o);
    if ((tid & 31) == 0) red[tid >> 5] = ss;
    __syncthreads();
    float tot = 0.0f;
    #pragma unroll
    for (int j = 0; j < 8; j++) tot += red[j];
    float inv = rsqrtf(tot);
    #pragma unroll
    for (int j = 0; j < 4; j++) {
        sre[tid + j * 256] = v[j] * inv;
        sim[tid + j * 256] = 0.0f;
    }
    __syncthreads();

    for (int g = 0; g < 30; g++) {
        const float Am = Ug[g][0], Bm = Ug[g][1];
        const float Cm = Ug[g][2], Dm = Ug[g][3];
        const unsigned m  = tab.m[g];
        const unsigned rr = tab.r[g];
        const unsigned pbm = rr & (0u - rr);       // lowest set bit of rr
        const unsigned lomask = pbm - 1;
        #pragma unroll
        for (int it = 0; it < 2; it++) {
            unsigned p = (unsigned)tid + it * 256; // 0..511
            unsigned lo = p & lomask;
            unsigned y0 = ((p ^ lo) << 1) | lo;    // insert 0 at pivot bit
            unsigned par = __popc(y0 & rr) & 1;
            unsigned i0 = y0 | (par ? pbm : 0u);   // logical bit = 0 side
            unsigned i1 = i0 ^ m;                  // logical bit = 1 partner
            float a0r = sre[i0], a0i = sim[i0];
            float a1r = sre[i1], a1i = sim[i1];
            sre[i0] = Am * a0r + Bm * a0i - Cm * a1r + Dm * a1i;
            sim[i0] = Am * a0i - Bm * a0r - Cm * a1i - Dm * a1r;
            sre[i1] = Cm * a0r + Dm * a0i + Am * a1r - Bm * a1i;
            sim[i1] = Cm * a0i - Dm * a0r + Am * a1i + Bm * a1r;
        }
        __syncthreads();
    }

    // probs at logical index b live at physical P(b) -> ext bf16 (hi|lo|hi)
    size_t base = (size_t)row * 3072;
    #pragma unroll
    for (int j = 0; j < 4; j++) {
        int b = tid + j * 256;
        unsigned phys = 0;
        #pragma unroll
        for (int k2 = 0; k2 < 10; k2++)
            if ((b >> k2) & 1) phys ^= tab.fcol[k2];
        float pre = sre[phys], pim = sim[phys];
        float p = pre * pre + pim * pim;
        __nv_bfloat16 hi = __float2bfloat16(p);
        __nv_bfloat16 lo = __float2bfloat16(p - __bfloat162float(hi));
        out[base + b] = hi;
        out[base + 1024 + b] = lo;
        out[base + 2048 + b] = hi;
    }
}

// ---------------------------------------------------------------------------
// Final: y = |x| ; y /= rowsum(y)   x: [4096, 1024-strided], out: [4096, 1000]
// ---------------------------------------------------------------------------
__global__ __launch_bounds__(256) void abs_norm_kernel(
    const float* __restrict__ x, float* __restrict__ out)
{
    __shared__ float red[8];
    const int row = blockIdx.x;
    const int tid = threadIdx.x;

    float v[4];
    float ss = 0.0f;
    #pragma unroll
    for (int j = 0; j < 4; j++) {
        int i = tid + j * 256;
        v[j] = (i < 1000) ? fabsf(x[(size_t)row * 1024 + i]) : 0.0f;
        ss += v[j];
    }
    #pragma unroll
    for (int o = 16; o > 0; o >>= 1)
        ss += __shfl_xor_sync(0xFFFFFFFFu, ss, o);
    if ((tid & 31) == 0) red[tid >> 5] = ss;
    __syncthreads();
    float tot = 0.0f;
    #pragma unroll
    for (int j = 0; j < 8; j++) tot += red[j];
    float inv = 1.0f / tot;
    #pragma unroll
    for (int j = 0; j < 4; j++) {
        int i = tid + j * 256;
        if (i < 1000)
            out[(size_t)row * 1000 + i] = v[j] * inv;
    }
}

// ---------------------------------------------------------------------------
// Host: compute circuit schedule (structure-only, weight-independent).
// ---------------------------------------------------------------------------
static CircTab make_circ_tab()
{
    unsigned pc[10], pr[10];
    for (int j = 0; j < 10; j++) { pc[j] = 1u << j; pr[j] = 1u << j; }
    CircTab t;
    for (int l = 0; l < 3; l++) {
        for (int q = 0; q < 10; q++) {
            int g = l * 10 + q, b = 9 - q;          // wire q <-> bit 9-q
            t.m[g] = (unsigned short)pc[b];
            t.r[g] = (unsigned short)pr[b];
        }
        int rr = l % 9 + 1;
        for (int q = 0; q < 10; q++) {
            int c = 9 - q;                           // control bit
            int tt = 9 - ((q + rr) % 10);            // target bit
            pc[c] ^= pc[tt];                         // P' = P * C (column op)
            pr[tt] ^= pr[c];                         // P'^-1 = C * P^-1 (row op)
        }
    }
    for (int j = 0; j < 10; j++) t.fcol[j] = (unsigned short)pc[j];
    return t;
}

// ---------------------------------------------------------------------------
// Launch
// ---------------------------------------------------------------------------
extern "C" void kernel_launch(void* const* d_in, const int* in_sizes, int n_in,
                              void* d_out, int out_size)
{
    const float* inputs = (const float*)d_in[0];
    const float* wEnc   = (const float*)d_in[1];
    const float* wDec   = (const float*)d_in[2];
    const float* W0     = (const float*)d_in[3];
    const float* b0     = (const float*)d_in[4];
    const float* W1     = (const float*)d_in[5];
    const float* b1     = (const float*)d_in[6];
    const float* W2     = (const float*)d_in[7];
    const float* b2     = (const float*)d_in[8];
    const float* W3     = (const float*)d_in[9];
    const float* b3     = (const float*)d_in[10];
    float* outp = (float*)d_out;

    float *bufA = nullptr, *bufB = nullptr, *bias3 = nullptr, *biasC = nullptr,
          *wcPart = nullptr;
    __nv_bfloat16 *actx2 = nullptr, *w0x = nullptr, *w1e = nullptr,
                  *w2x = nullptr, *w3x = nullptr, *wcx = nullptr;
    cudaGetSymbolAddress((void**)&bufA, g_bufA);
    cudaGetSymbolAddress((void**)&bufB, g_bufB);
    cudaGetSymbolAddress((void**)&bias3, g_bias3);
    cudaGetSymbolAddress((void**)&biasC, g_biasC);
    cudaGetSymbolAddress((void**)&wcPart, g_wcPart);
    cudaGetSymbolAddress((void**)&actx2, g_actx2);
    cudaGetSymbolAddress((void**)&w0x, g_w0x);
    cudaGetSymbolAddress((void**)&w1e, g_w1e);
    cudaGetSymbolAddress((void**)&w2x, g_w2x);
    cudaGetSymbolAddress((void**)&w3x, g_w3x);
    cudaGetSymbolAddress((void**)&wcx, g_wcx);

    const CircTab tab = make_circ_tab();

    dim3 blk(256);
    dim3 blkg(128);
    const int GSMEM = 2 * STAGE_BYTES;   // 65536 B dynamic smem (double buffer)
    cudaFuncSetAttribute(gemm_mma,
                         cudaFuncAttributeMaxDynamicSharedMemorySize, GSMEM);

    // ---- Weight prep (per-launch, deterministic) ----
    convert_weight<<<dim3(32, 32), blk>>>(W0, w0x, 1000, 1024, 1024, 1024);
    convert_weight<<<dim3(64, 32), blk>>>(W2, w2x, 2048, 1024, 2048, 1024);
    convert_weight<<<dim3(32, 32), blk>>>(W3, w3x, 1024, 1000, 1024, 1024);
    pad_bias<<<4, blk>>>(b3, bias3, 1000);

    // ---- Fuse W1@W2 -> Wc (split-K=4, deterministic partials + reduce) ----
    convert_act<<<1024 * 2048 / 256, blk>>>(W1, w1e, 2048, 2048);
    gemm_mma<<<dim3(8, 8, 4), blkg, GSMEM>>>(1536, 6144, 1024, 2,
                                             w1e, w2x, bias3, wcPart);
    reduce4<<<4096, blk>>>(wcPart, bufB);               // Wc fp32 [1024,1024]
    bias_compose<<<4, blk>>>(b1, W2, b2, biasC);        // bc = b1@W2 + b2
    convert_weight<<<dim3(32, 32), blk>>>(bufB, wcx, 1024, 1024, 1024, 1024);

    // ---- Main path ----
    // x = inputs @ W0 + b0                       [4096,1024] fp32
    convert_act<<<4096 * 1024 / 256, blk>>>(inputs, actx2, 1000, 1024);
    gemm_mma<<<dim3(8, 32), blkg, GSMEM>>>(3072, 3072, 1024, 0,
                                           actx2, w0x, b0, bufA);
    // x = circuit(x, wEnc) -> ext bf16
    circuit_kernel<<<4096, blk>>>(bufA, wEnc, tab, actx2);
    // x = x @ Wc + bc                            [4096,1024] fp32
    gemm_mma<<<dim3(8, 32), blkg, GSMEM>>>(3072, 3072, 1024, 0,
                                           actx2, wcx, biasC, bufA);
    // x = circuit(x, wDec) -> ext bf16
    circuit_kernel<<<4096, blk>>>(bufA, wDec, tab, actx2);
    // x = x @ W3 + b3                            [4096,1024-padded] fp32
    gemm_mma<<<dim3(8, 32), blkg, GSMEM>>>(3072, 3072, 1024, 0,
                                           actx2, w3x, bias3, bufB);
    // out = |x| / rowsum(|x|)
    abs_norm_kernel<<<4096, blk>>>(bufB, outp);
}